// round 3
// baseline (speedup 1.0000x reference)
#include <cuda_runtime.h>
#include <cstdint>

#define Bc 8
#define Lc 2048
#define Dc 1024
#define Fc 4096
#define Mc (Bc*Lc)          // 16384 rows
#define TOPK 7
#define NFFT 2048
#define DG 16               // d-channels per FFT block
#define NGRP (Dc/DG)        // 64 groups

// ---------------- scratch (device globals; no allocation) ----------------
__device__ float  g_q[Mc*Dc];
__device__ float  g_k[Mc*Dc];
__device__ float  g_v[Mc*Dc];
__device__ float  g_qT[Mc*Dc];
__device__ float  g_kT[Mc*Dc];
__device__ float2 g_Spart[Bc*NGRP*NFFT];
__device__ float  g_mean[Bc*NFFT];
__device__ float  g_topW[Bc*TOPK];
__device__ int    g_topI[Bc*TOPK];
__device__ float  g_aggv[Mc*Dc];
__device__ float  g_attn[Mc*Dc];
__device__ float  g_x1[Mc*Dc];
__device__ float  g_ffn1[Mc*Fc];
__device__ float  g_ffn2[Mc*Dc];

// ---------------- fp32 SGEMM: C = A[M,K] @ W[K,N] + bias (+relu) ----------------
#define SG_BM 128
#define SG_BN 128
#define SG_BK 8

__global__ __launch_bounds__(256, 2)
void sgemm_kernel(const float* __restrict__ A, const float* __restrict__ W,
                  const float* __restrict__ bias, float* __restrict__ C,
                  int M, int N, int K, int relu)
{
    __shared__ float As[SG_BK][SG_BM];
    __shared__ float Bs[SG_BK][SG_BN];
    int tid = threadIdx.x;
    int tx = tid & 15, ty = tid >> 4;

    size_t arow0 = (size_t)blockIdx.y * SG_BM;
    size_t bcol0 = (size_t)blockIdx.x * SG_BN;
    const float* Ap = A + arow0 * (size_t)K;
    const float* Wp = W + bcol0;

    int a_r = tid >> 1, a_c = (tid & 1) << 2;     // A: 128 rows x 8 cols, float4 per thread
    int b_r = tid >> 5, b_c = (tid & 31) << 2;    // B: 8 rows x 128 cols, float4 per thread

    float acc[8][8];
#pragma unroll
    for (int i = 0; i < 8; i++)
#pragma unroll
        for (int j = 0; j < 8; j++) acc[i][j] = 0.0f;

    float4 av = *(const float4*)(Ap + (size_t)a_r * K + a_c);
    float4 bv = *(const float4*)(Wp + (size_t)b_r * N + b_c);

    for (int k0 = 0; k0 < K; k0 += SG_BK) {
        As[a_c + 0][a_r] = av.x;
        As[a_c + 1][a_r] = av.y;
        As[a_c + 2][a_r] = av.z;
        As[a_c + 3][a_r] = av.w;
        *(float4*)&Bs[b_r][b_c] = bv;
        __syncthreads();

        float4 avn = av, bvn = bv;
        if (k0 + SG_BK < K) {
            avn = *(const float4*)(Ap + (size_t)a_r * K + (k0 + SG_BK) + a_c);
            bvn = *(const float4*)(Wp + (size_t)(k0 + SG_BK + b_r) * N + b_c);
        }

#pragma unroll
        for (int kk = 0; kk < SG_BK; kk++) {
            float4 a0 = *(const float4*)&As[kk][ty * 8];
            float4 a1 = *(const float4*)&As[kk][ty * 8 + 4];
            float4 b0 = *(const float4*)&Bs[kk][tx * 8];
            float4 b1 = *(const float4*)&Bs[kk][tx * 8 + 4];
            float ar[8] = {a0.x, a0.y, a0.z, a0.w, a1.x, a1.y, a1.z, a1.w};
            float br[8] = {b0.x, b0.y, b0.z, b0.w, b1.x, b1.y, b1.z, b1.w};
#pragma unroll
            for (int i = 0; i < 8; i++)
#pragma unroll
                for (int j = 0; j < 8; j++)
                    acc[i][j] = fmaf(ar[i], br[j], acc[i][j]);
        }
        __syncthreads();
        av = avn; bv = bvn;
    }

    float bre[8];
#pragma unroll
    for (int j = 0; j < 8; j++) bre[j] = bias[bcol0 + tx * 8 + j];

#pragma unroll
    for (int i = 0; i < 8; i++) {
        size_t r = arow0 + (size_t)ty * 8 + i;
        float* Crow = C + r * (size_t)N + bcol0 + tx * 8;
#pragma unroll
        for (int j = 0; j < 8; j++) {
            float vv = acc[i][j] + bre[j];
            if (relu) vv = fmaxf(vv, 0.0f);
            Crow[j] = vv;
        }
    }
}

// ---------------- transpose [B,L,D] -> [B,D,L] ----------------
__global__ void transpose_kernel(const float* __restrict__ in, float* __restrict__ out)
{
    __shared__ float tile[32][33];
    int bb = blockIdx.z;
    int l0 = blockIdx.x << 5;
    int d0 = blockIdx.y << 5;
    const float* ip = in + (size_t)bb * Lc * Dc;
    float* op = out + (size_t)bb * Lc * Dc;
    int tx = threadIdx.x, ty = threadIdx.y;
#pragma unroll
    for (int i = ty; i < 32; i += 8)
        tile[i][tx] = ip[(size_t)(l0 + i) * Dc + d0 + tx];
    __syncthreads();
#pragma unroll
    for (int i = ty; i < 32; i += 8)
        op[(size_t)(d0 + i) * Lc + l0 + tx] = tile[tx][i];
}

// ---------------- shared-memory 2048-point Stockham FFT ----------------
#define IDX(i) ((i) + ((i) >> 4))   // pad to avoid stride-16 bank conflicts

__device__ __forceinline__ float2 cmulf(float2 a, float2 b)
{
    return make_float2(fmaf(a.x, b.x, -a.y * b.y), fmaf(a.x, b.y, a.y * b.x));
}

// 11 Stockham stages. 256 threads. Input in bufA (padded). Returns result buffer.
__device__ float2* fft2048_shared(float2* bufA, float2* bufB, const float2* tw, int tid)
{
    float2* x = bufA;
    float2* y = bufB;
#pragma unroll
    for (int ls = 0; ls < 11; ls++) {
        int half  = 1024 >> ls;
        int smask = (1 << ls) - 1;
        __syncthreads();
#pragma unroll
        for (int r = 0; r < 4; r++) {
            int i  = tid + (r << 8);
            int qq = i & smask;
            int p  = i >> ls;
            float2 a  = x[IDX(qq + (p << ls))];
            float2 bb = x[IDX(qq + ((p + half) << ls))];
            float2 w  = tw[IDX(p << ls)];
            float2 su = make_float2(a.x + bb.x, a.y + bb.y);
            float2 di = make_float2(a.x - bb.x, a.y - bb.y);
            y[IDX(qq + ((2 * p) << ls))]     = su;
            y[IDX(qq + ((2 * p + 1) << ls))] = cmulf(di, w);
        }
        float2* t = x; x = y; y = t;
    }
    __syncthreads();
    return x;
}

// Forward: z = q + i*k per channel; accumulate P[f] = Q[f]*conj(K[f]) over DG channels.
__global__ __launch_bounds__(256)
void autocorr_fft_kernel(const float* __restrict__ qT, const float* __restrict__ kT,
                         float2* __restrict__ Spart)
{
    __shared__ float2 bufA[2176];
    __shared__ float2 bufB[2176];
    __shared__ float2 tw[1088];
    int tid = threadIdx.x;
    int b = blockIdx.x / NGRP;
    int g = blockIdx.x % NGRP;

    for (int p = tid; p < 1024; p += 256) {
        float s, c;
        sincospif(-2.0f * (float)p / 2048.0f, &s, &c);
        tw[IDX(p)] = make_float2(c, s);
    }

    float2 acc[8];
#pragma unroll
    for (int r = 0; r < 8; r++) acc[r] = make_float2(0.0f, 0.0f);

    for (int dd = 0; dd < DG; dd++) {
        int d = g * DG + dd;
        const float* qrow = qT + ((size_t)b * Dc + d) * (size_t)Lc;
        const float* krow = kT + ((size_t)b * Dc + d) * (size_t)Lc;
        for (int t = tid; t < NFFT; t += 256)
            bufA[IDX(t)] = make_float2(qrow[t], krow[t]);

        float2* Z = fft2048_shared(bufA, bufB, tw, tid);

#pragma unroll
        for (int r = 0; r < 8; r++) {
            int f = tid + (r << 8);
            float2 zf = Z[IDX(f)];
            float2 zr = Z[IDX((NFFT - f) & (NFFT - 1))];
            // Q[f] = (Z[f] + conj(Z[N-f]))/2 ; K[f] = (Z[f] - conj(Z[N-f]))/(2i)
            float qx = 0.5f * (zf.x + zr.x), qy = 0.5f * (zf.y - zr.y);
            float dx = zf.x - zr.x,          dy = zf.y + zr.y;
            float kx = 0.5f * dy,            ky = -0.5f * dx;
            // P = Q * conj(K)
            acc[r].x += qx * kx + qy * ky;
            acc[r].y += qy * kx - qx * ky;
        }
    }

    float2* outp = Spart + ((size_t)b * NGRP + g) * NFFT;
#pragma unroll
    for (int r = 0; r < 8; r++) outp[tid + (r << 8)] = acc[r];
}

// Inverse: reduce partials over groups, IDFT, scale by 1/(L*D) -> mean_value[b, tau]
__global__ __launch_bounds__(256)
void ifft_mean_kernel(const float2* __restrict__ Spart, float* __restrict__ meanv)
{
    __shared__ float2 bufA[2176];
    __shared__ float2 bufB[2176];
    __shared__ float2 tw[1088];
    int tid = threadIdx.x;
    int b = blockIdx.x;

    for (int p = tid; p < 1024; p += 256) {
        float s, c;
        sincospif(2.0f * (float)p / 2048.0f, &s, &c);
        tw[IDX(p)] = make_float2(c, s);
    }
    for (int t = tid; t < NFFT; t += 256) {
        float2 s = make_float2(0.0f, 0.0f);
        const float2* base = Spart + (size_t)b * NGRP * NFFT + t;
        for (int g2 = 0; g2 < NGRP; g2++) {
            float2 vv = base[(size_t)g2 * NFFT];
            s.x += vv.x; s.y += vv.y;
        }
        bufA[IDX(t)] = s;
    }

    float2* Z = fft2048_shared(bufA, bufB, tw, tid);

    const float scale = 1.0f / (2048.0f * 1024.0f);
    for (int t = tid; t < NFFT; t += 256)
        meanv[b * NFFT + t] = Z[IDX(t)].x * scale;
}

// ---------------- top-7 + softmax (matches jax.lax.top_k tie-breaking) ----------------
__global__ __launch_bounds__(256)
void topk_kernel(const float* __restrict__ meanv, float* __restrict__ topW, int* __restrict__ topI)
{
    __shared__ float vals[NFFT];
    __shared__ float rv[256];
    __shared__ int   ri[256];
    __shared__ float sv[TOPK];
    __shared__ int   si[TOPK];
    int b = blockIdx.x, tid = threadIdx.x;

    for (int t = tid; t < NFFT; t += 256) vals[t] = meanv[b * NFFT + t];
    __syncthreads();

    for (int it = 0; it < TOPK; it++) {
        float best = -3.4e38f; int bi = 1 << 30;
        for (int t = tid; t < NFFT; t += 256) {
            float vv = vals[t];
            if (vv > best) { best = vv; bi = t; }   // ascending scan: keeps lowest idx on tie
        }
        rv[tid] = best; ri[tid] = bi;
        __syncthreads();
        for (int off = 128; off > 0; off >>= 1) {
            if (tid < off) {
                float v2 = rv[tid + off]; int i2 = ri[tid + off];
                if (v2 > rv[tid] || (v2 == rv[tid] && i2 < ri[tid])) { rv[tid] = v2; ri[tid] = i2; }
            }
            __syncthreads();
        }
        if (tid == 0) { sv[it] = rv[0]; si[it] = ri[0]; vals[ri[0]] = -3.4e38f; }
        __syncthreads();
    }

    if (tid == 0) {
        float mx = sv[0], ssum = 0.0f, e[TOPK];
        for (int i = 0; i < TOPK; i++) { e[i] = expf(sv[i] - mx); ssum += e[i]; }
        for (int i = 0; i < TOPK; i++) {
            topW[b * TOPK + i] = e[i] / ssum;
            topI[b * TOPK + i] = si[i];
        }
    }
}

// ---------------- weighted roll-aggregate of v ----------------
// out[b,l,:] = sum_i w[b,i] * v[b, (l + delay_i) % L, :], delay_i from batch 0
__global__ __launch_bounds__(256)
void agg_roll_kernel(const float* __restrict__ v, const float* __restrict__ topW,
                     const int* __restrict__ topI, float* __restrict__ out)
{
    __shared__ float w[8];
    __shared__ int   dl[8];
    int row = blockIdx.x;
    int b = row >> 11;          // / 2048
    int l = row & (Lc - 1);
    int tid = threadIdx.x;
    if (tid < TOPK) { w[tid] = topW[b * TOPK + tid]; dl[tid] = topI[tid]; }
    __syncthreads();

    float4 acc = make_float4(0.f, 0.f, 0.f, 0.f);
#pragma unroll
    for (int i = 0; i < TOPK; i++) {
        int src = l + dl[i];
        if (src >= Lc) src -= Lc;
        float4 t = *(const float4*)(v + ((size_t)b * Lc + src) * Dc + tid * 4);
        float wi = w[i];
        acc.x = fmaf(wi, t.x, acc.x);
        acc.y = fmaf(wi, t.y, acc.y);
        acc.z = fmaf(wi, t.z, acc.z);
        acc.w = fmaf(wi, t.w, acc.w);
    }
    *(float4*)(out + (size_t)row * Dc + tid * 4) = acc;
}

// ---------------- residual add + LayerNorm ----------------
__global__ __launch_bounds__(256)
void add_ln_kernel(const float* __restrict__ A, const float* __restrict__ Rv,
                   const float* __restrict__ gam, const float* __restrict__ bet,
                   float* __restrict__ out)
{
    __shared__ float red1[8];
    __shared__ float red2[8];
    int row = blockIdx.x, tid = threadIdx.x;
    const float4* a4 = (const float4*)(A + (size_t)row * Dc);
    const float4* r4 = (const float4*)(Rv + (size_t)row * Dc);
    float4 va = a4[tid], vr = r4[tid];
    float4 s = make_float4(va.x + vr.x, va.y + vr.y, va.z + vr.z, va.w + vr.w);

    float part = s.x + s.y + s.z + s.w;
#pragma unroll
    for (int o = 16; o; o >>= 1) part += __shfl_xor_sync(0xffffffffu, part, o);
    if ((tid & 31) == 0) red1[tid >> 5] = part;
    __syncthreads();
    float tot = red1[0] + red1[1] + red1[2] + red1[3] + red1[4] + red1[5] + red1[6] + red1[7];
    float mean = tot * (1.0f / (float)Dc);

    float d0 = s.x - mean, d1 = s.y - mean, d2 = s.z - mean, d3 = s.w - mean;
    float p2 = d0 * d0 + d1 * d1 + d2 * d2 + d3 * d3;
#pragma unroll
    for (int o = 16; o; o >>= 1) p2 += __shfl_xor_sync(0xffffffffu, p2, o);
    if ((tid & 31) == 0) red2[tid >> 5] = p2;
    __syncthreads();
    float tot2 = red2[0] + red2[1] + red2[2] + red2[3] + red2[4] + red2[5] + red2[6] + red2[7];
    float var = tot2 * (1.0f / (float)Dc);
    float inv = rsqrtf(var + 1e-6f);

    float4 gg = ((const float4*)gam)[tid];
    float4 bb = ((const float4*)bet)[tid];
    float4 o4 = make_float4(d0 * inv * gg.x + bb.x,
                            d1 * inv * gg.y + bb.y,
                            d2 * inv * gg.z + bb.z,
                            d3 * inv * gg.w + bb.w);
    ((float4*)(out + (size_t)row * Dc))[tid] = o4;
}

// ---------------- launch ----------------
extern "C" void kernel_launch(void* const* d_in, const int* in_sizes, int n_in,
                              void* d_out, int out_size)
{
    const float* x    = (const float*)d_in[0];
    const float* Wq   = (const float*)d_in[1];
    const float* bq   = (const float*)d_in[2];
    const float* Wk   = (const float*)d_in[3];
    const float* bk   = (const float*)d_in[4];
    const float* Wv   = (const float*)d_in[5];
    const float* bv   = (const float*)d_in[6];
    const float* Wo   = (const float*)d_in[7];
    const float* bo   = (const float*)d_in[8];
    const float* ln1g = (const float*)d_in[9];
    const float* ln1b = (const float*)d_in[10];
    const float* c1w  = (const float*)d_in[11];
    const float* c1b  = (const float*)d_in[12];
    const float* c2w  = (const float*)d_in[13];
    const float* c2b  = (const float*)d_in[14];
    const float* ln2g = (const float*)d_in[15];
    const float* ln2b = (const float*)d_in[16];
    float* out = (float*)d_out;

    float *q, *k, *v, *qT, *kT, *meanv, *topW, *aggv, *attn, *x1, *ffn1, *ffn2;
    float2* Spart; int* topI;
    cudaGetSymbolAddress((void**)&q,     g_q);
    cudaGetSymbolAddress((void**)&k,     g_k);
    cudaGetSymbolAddress((void**)&v,     g_v);
    cudaGetSymbolAddress((void**)&qT,    g_qT);
    cudaGetSymbolAddress((void**)&kT,    g_kT);
    cudaGetSymbolAddress((void**)&Spart, g_Spart);
    cudaGetSymbolAddress((void**)&meanv, g_mean);
    cudaGetSymbolAddress((void**)&topW,  g_topW);
    cudaGetSymbolAddress((void**)&topI,  g_topI);
    cudaGetSymbolAddress((void**)&aggv,  g_aggv);
    cudaGetSymbolAddress((void**)&attn,  g_attn);
    cudaGetSymbolAddress((void**)&x1,    g_x1);
    cudaGetSymbolAddress((void**)&ffn1,  g_ffn1);
    cudaGetSymbolAddress((void**)&ffn2,  g_ffn2);

    dim3 gD(Dc / SG_BN, Mc / SG_BM);   // (8, 128)
    dim3 gF(Fc / SG_BN, Mc / SG_BM);   // (32, 128)
    dim3 gT(Lc / 32, Dc / 32, Bc);
    dim3 bT(32, 8);

    sgemm_kernel<<<gD, 256>>>(x, Wq, bq, q, Mc, Dc, Dc, 0);
    sgemm_kernel<<<gD, 256>>>(x, Wk, bk, k, Mc, Dc, Dc, 0);
    sgemm_kernel<<<gD, 256>>>(x, Wv, bv, v, Mc, Dc, Dc, 0);

    transpose_kernel<<<gT, bT>>>(q, qT);
    transpose_kernel<<<gT, bT>>>(k, kT);

    autocorr_fft_kernel<<<Bc * NGRP, 256>>>(qT, kT, Spart);
    ifft_mean_kernel<<<Bc, 256>>>(Spart, meanv);
    topk_kernel<<<Bc, 256>>>(meanv, topW, topI);
    agg_roll_kernel<<<Mc, 256>>>(v, topW, topI, aggv);

    sgemm_kernel<<<gD, 256>>>(aggv, Wo, bo, attn, Mc, Dc, Dc, 0);
    add_ln_kernel<<<Mc, 256>>>(x, attn, ln1g, ln1b, x1);

    sgemm_kernel<<<gF, 256>>>(x1, c1w, c1b, ffn1, Mc, Fc, Dc, 1);
    sgemm_kernel<<<gD, 256>>>(ffn1, c2w, c2b, ffn2, Mc, Dc, Fc, 0);
    add_ln_kernel<<<Mc, 256>>>(x1, ffn2, ln2g, ln2b, out);
}

// round 10
// speedup vs baseline: 2.3947x; 2.3947x over previous
#include <cuda_runtime.h>
#include <cuda_bf16.h>
#include <cstdint>

#define Bc 8
#define Lc 2048
#define Dc 1024
#define Fc 4096
#define Mc (Bc*Lc)          // 16384 rows
#define TOPK 7
#define NFFT 2048
#define DG 16               // d-channels per FFT block
#define NGRP (Dc/DG)        // 64 groups

// ================= scratch (device globals) =================
__device__ float  g_q[Mc*Dc];
__device__ float  g_k[Mc*Dc];
__device__ float  g_v[Mc*Dc];
__device__ float  g_qT[Mc*Dc];
__device__ float  g_kT[Mc*Dc];
__device__ float2 g_Spart[Bc*NGRP*NFFT];
__device__ float  g_mean[Bc*NFFT];
__device__ float  g_topW[Bc*TOPK];
__device__ int    g_topI[Bc*TOPK];
__device__ float  g_attn[Mc*Dc];
__device__ float  g_x1[Mc*Dc];
__device__ float  g_ffn2[Mc*Dc];

__device__ __nv_bfloat16 g_xh[Mc*Dc],  g_xl[Mc*Dc];
__device__ __nv_bfloat16 g_aggh[Mc*Dc], g_aggl[Mc*Dc];
__device__ __nv_bfloat16 g_x1h[Mc*Dc], g_x1l[Mc*Dc];
__device__ __nv_bfloat16 g_f1h[Mc*Fc], g_f1l[Mc*Fc];
__device__ __nv_bfloat16 g_wqh[Dc*Dc], g_wql[Dc*Dc];
__device__ __nv_bfloat16 g_wkh[Dc*Dc], g_wkl[Dc*Dc];
__device__ __nv_bfloat16 g_wvh[Dc*Dc], g_wvl[Dc*Dc];
__device__ __nv_bfloat16 g_woh[Dc*Dc], g_wol[Dc*Dc];
__device__ __nv_bfloat16 g_c1h[Fc*Dc], g_c1l[Fc*Dc];
__device__ __nv_bfloat16 g_c2h[Dc*Fc], g_c2l[Dc*Fc];

// ================= split helpers =================
__device__ __forceinline__ void split1(float v, __nv_bfloat16& h, __nv_bfloat16& l) {
    h = __float2bfloat16(v);
    l = __float2bfloat16(v - __bfloat162float(h));
}

__global__ __launch_bounds__(256)
void split_kernel(const float* __restrict__ in, __nv_bfloat16* __restrict__ hi,
                  __nv_bfloat16* __restrict__ lo, int n4)
{
    int i = blockIdx.x * 256 + threadIdx.x;
    if (i >= n4) return;
    float4 v = ((const float4*)in)[i];
    __nv_bfloat16 h0, h1, h2, h3, l0, l1, l2, l3;
    split1(v.x, h0, l0); split1(v.y, h1, l1); split1(v.z, h2, l2); split1(v.w, h3, l3);
    __nv_bfloat162* hp = (__nv_bfloat162*)hi;
    __nv_bfloat162* lp = (__nv_bfloat162*)lo;
    hp[2*i]   = __halves2bfloat162(h0, h1);
    hp[2*i+1] = __halves2bfloat162(h2, h3);
    lp[2*i]   = __halves2bfloat162(l0, l1);
    lp[2*i+1] = __halves2bfloat162(l2, l3);
}

// W[K,N] fp32 -> T[N,K] bf16 hi/lo
__global__ void wtrans_split_kernel(const float* __restrict__ W, __nv_bfloat16* __restrict__ Th,
                                    __nv_bfloat16* __restrict__ Tl, int K, int N)
{
    __shared__ float tile[32][33];
    int k0 = blockIdx.y << 5, n0 = blockIdx.x << 5;
    int tx = threadIdx.x, ty = threadIdx.y;
#pragma unroll
    for (int i = ty; i < 32; i += 8)
        tile[i][tx] = W[(size_t)(k0 + i) * N + n0 + tx];
    __syncthreads();
#pragma unroll
    for (int i = ty; i < 32; i += 8) {
        float v = tile[tx][i];
        __nv_bfloat16 h, l; split1(v, h, l);
        size_t o = (size_t)(n0 + i) * K + k0 + tx;
        Th[o] = h; Tl[o] = l;
    }
}

// ================= HMMA split-bf16 GEMM (mma.sync, base sm_103 target) =================
// C[128x128 tile] = Ahi*Bhi + Ahi*Blo + Alo*Bhi  (fp32 accum)
// A[M,K] bf16 row-major; B[N,K] bf16 row-major (pre-transposed weights)
// mode 0: C fp32 = D + bias ; mode 1: relu(D+bias) split -> Chi/Clo bf16

#define GM_BK 32
#define GM_PADB 80                       // bytes per smem row (32 elems used + 8 pad)
#define MAT_BYTES (128*GM_PADB)          // 10240
#define STAGE_BYTES (4*MAT_BYTES)        // 40960 (Ahi,Alo,Bhi,Blo)
#define GM_SMEM_TOTAL (2*STAGE_BYTES)    // 81920

__device__ __forceinline__ uint32_t smem_u32(const void* p) {
    uint32_t a;
    asm("{ .reg .u64 t; cvta.to.shared.u64 t, %1; cvt.u32.u64 %0, t; }" : "=r"(a) : "l"(p));
    return a;
}
__device__ __forceinline__ void cp16(uint32_t s, const void* g) {
    asm volatile("cp.async.cg.shared.global [%0], [%1], 16;" :: "r"(s), "l"(g) : "memory");
}
__device__ __forceinline__ void ldsm4(uint32_t* r, uint32_t a) {
    asm volatile("ldmatrix.sync.aligned.m8n8.x4.shared.b16 {%0,%1,%2,%3}, [%4];"
                 : "=r"(r[0]), "=r"(r[1]), "=r"(r[2]), "=r"(r[3]) : "r"(a));
}
__device__ __forceinline__ void mma16816(float* d, const uint32_t* a, uint32_t b0, uint32_t b1) {
    asm volatile("mma.sync.aligned.m16n8k16.row.col.f32.bf16.bf16.f32 "
                 "{%0,%1,%2,%3}, {%4,%5,%6,%7}, {%8,%9}, {%0,%1,%2,%3};"
                 : "+f"(d[0]), "+f"(d[1]), "+f"(d[2]), "+f"(d[3])
                 : "r"(a[0]), "r"(a[1]), "r"(a[2]), "r"(a[3]), "r"(b0), "r"(b1));
}

__device__ __forceinline__ void load_chunk(uint32_t sbase,
    const __nv_bfloat16* pAh, const __nv_bfloat16* pAl,
    const __nv_bfloat16* pBh, const __nv_bfloat16* pBl,
    int K, int ko, int tid)
{
    const __nv_bfloat16* srcs[4] = {pAh + ko, pAl + ko, pBh + ko, pBl + ko};
#pragma unroll
    for (int m = 0; m < 4; m++) {
        const __nv_bfloat16* src = srcs[m];
        uint32_t mb = sbase + m * MAT_BYTES;
#pragma unroll
        for (int t = 0; t < 2; t++) {
            int idx = tid + t * 256;
            int r = idx >> 2, cs = idx & 3;
            cp16(mb + r * GM_PADB + cs * 16, src + (size_t)r * K + cs * 8);
        }
    }
}

__global__ __launch_bounds__(256)
void gemm_hmma3(const __nv_bfloat16* __restrict__ Ahi, const __nv_bfloat16* __restrict__ Alo,
                const __nv_bfloat16* __restrict__ Bhi, const __nv_bfloat16* __restrict__ Blo,
                const float* __restrict__ bias,
                float* __restrict__ C, __nv_bfloat16* __restrict__ Chi, __nv_bfloat16* __restrict__ Clo,
                int M, int N, int K, int mode, int NB)
{
    extern __shared__ char smem[];
    uint32_t sb = smem_u32(smem);
    int tid = threadIdx.x, lane = tid & 31, warp = tid >> 5;

    // CTA swizzle: panels of 8 along M for L2 reuse
    int bid = blockIdx.x;
    int panel  = bid / (8 * NB);
    int within = bid - panel * (8 * NB);
    int bm = panel * 8 + (within & 7);
    int bn = within >> 3;
    size_t row0 = (size_t)bm * 128, col0 = (size_t)bn * 128;

    const __nv_bfloat16* pAh = Ahi + row0 * (size_t)K;
    const __nv_bfloat16* pAl = Alo + row0 * (size_t)K;
    const __nv_bfloat16* pBh = Bhi + col0 * (size_t)K;
    const __nv_bfloat16* pBl = Blo + col0 * (size_t)K;

    load_chunk(sb, pAh, pAl, pBh, pBl, K, 0, tid);
    asm volatile("cp.async.commit_group;" ::: "memory");

    // ldmatrix per-lane offsets (within a stage)
    int g = lane >> 3, rl = lane & 7;
    int wm = warp >> 1, wn = warp & 1;
    uint32_t aoff[2][2], boff[4][2];
#pragma unroll
    for (int i = 0; i < 2; i++)
#pragma unroll
        for (int ks = 0; ks < 2; ks++) {
            int row = wm * 32 + i * 16 + (g & 1) * 8 + rl;
            int col = ks * 16 + (g >> 1) * 8;
            aoff[i][ks] = row * GM_PADB + col * 2;
        }
#pragma unroll
    for (int j = 0; j < 4; j++)
#pragma unroll
        for (int ks = 0; ks < 2; ks++) {
            int row = wn * 64 + j * 16 + ((g >> 1) & 1) * 8 + rl;
            int col = ks * 16 + (g & 1) * 8;
            boff[j][ks] = 2 * MAT_BYTES + row * GM_PADB + col * 2;
        }

    float acc[2][8][4];
#pragma unroll
    for (int i = 0; i < 2; i++)
#pragma unroll
        for (int j = 0; j < 8; j++)
#pragma unroll
            for (int r = 0; r < 4; r++) acc[i][j][r] = 0.0f;

    int NC = K >> 5;
    for (int c = 0; c < NC; c++) {
        uint32_t sstage = sb + (uint32_t)(c & 1) * STAGE_BYTES;
        if (c + 1 < NC) {
            load_chunk(sb + (uint32_t)((c + 1) & 1) * STAGE_BYTES,
                       pAh, pAl, pBh, pBl, K, (c + 1) << 5, tid);
            asm volatile("cp.async.commit_group;" ::: "memory");
            asm volatile("cp.async.wait_group 1;" ::: "memory");
        } else {
            asm volatile("cp.async.wait_group 0;" ::: "memory");
        }
        __syncthreads();

#pragma unroll
        for (int ks = 0; ks < 2; ks++) {
            uint32_t ah[2][4], al[2][4];
            ldsm4(ah[0], sstage + aoff[0][ks]);
            ldsm4(ah[1], sstage + aoff[1][ks]);
            ldsm4(al[0], sstage + MAT_BYTES + aoff[0][ks]);
            ldsm4(al[1], sstage + MAT_BYTES + aoff[1][ks]);
#pragma unroll
            for (int j = 0; j < 4; j++) {
                uint32_t bh[4], bl[4];
                ldsm4(bh, sstage + boff[j][ks]);
                ldsm4(bl, sstage + MAT_BYTES + boff[j][ks]);
#pragma unroll
                for (int i = 0; i < 2; i++) {
                    mma16816(acc[i][2*j],   ah[i], bh[0], bh[1]);
                    mma16816(acc[i][2*j],   ah[i], bl[0], bl[1]);
                    mma16816(acc[i][2*j],   al[i], bh[0], bh[1]);
                    mma16816(acc[i][2*j+1], ah[i], bh[2], bh[3]);
                    mma16816(acc[i][2*j+1], ah[i], bl[2], bl[3]);
                    mma16816(acc[i][2*j+1], al[i], bh[2], bh[3]);
                }
            }
        }
        __syncthreads();
    }

    // epilogue
    int tr = lane >> 2, tc = (lane & 3) * 2;
#pragma unroll
    for (int i = 0; i < 2; i++) {
#pragma unroll
        for (int j = 0; j < 8; j++) {
            size_t r0 = row0 + wm * 32 + i * 16 + tr;
            size_t cl = col0 + wn * 64 + j * 8 + tc;
            float b0 = __ldg(bias + cl), b1 = __ldg(bias + cl + 1);
            float v00 = acc[i][j][0] + b0, v01 = acc[i][j][1] + b1;
            float v10 = acc[i][j][2] + b0, v11 = acc[i][j][3] + b1;
            if (mode == 0) {
                *(float2*)(C + r0 * (size_t)N + cl)       = make_float2(v00, v01);
                *(float2*)(C + (r0 + 8) * (size_t)N + cl) = make_float2(v10, v11);
            } else {
                v00 = fmaxf(v00, 0.f); v01 = fmaxf(v01, 0.f);
                v10 = fmaxf(v10, 0.f); v11 = fmaxf(v11, 0.f);
                __nv_bfloat16 h0,h1,h2,h3, l0,l1,l2,l3;
                split1(v00,h0,l0); split1(v01,h1,l1); split1(v10,h2,l2); split1(v11,h3,l3);
                *(__nv_bfloat162*)(Chi + r0 * (size_t)N + cl)       = __halves2bfloat162(h0, h1);
                *(__nv_bfloat162*)(Chi + (r0 + 8) * (size_t)N + cl) = __halves2bfloat162(h2, h3);
                *(__nv_bfloat162*)(Clo + r0 * (size_t)N + cl)       = __halves2bfloat162(l0, l1);
                *(__nv_bfloat162*)(Clo + (r0 + 8) * (size_t)N + cl) = __halves2bfloat162(l2, l3);
            }
        }
    }
}

// ================= transpose [B,L,D] -> [B,D,L] =================
__global__ void transpose_kernel(const float* __restrict__ in, float* __restrict__ out)
{
    __shared__ float tile[32][33];
    int bb = blockIdx.z;
    int l0 = blockIdx.x << 5;
    int d0 = blockIdx.y << 5;
    const float* ip = in + (size_t)bb * Lc * Dc;
    float* op = out + (size_t)bb * Lc * Dc;
    int tx = threadIdx.x, ty = threadIdx.y;
#pragma unroll
    for (int i = ty; i < 32; i += 8)
        tile[i][tx] = ip[(size_t)(l0 + i) * Dc + d0 + tx];
    __syncthreads();
#pragma unroll
    for (int i = ty; i < 32; i += 8)
        op[(size_t)(d0 + i) * Lc + l0 + tx] = tile[tx][i];
}

// ================= shared-memory 2048-point Stockham FFT =================
#define IDX(i) ((i) + ((i) >> 4))

__device__ __forceinline__ float2 cmulf(float2 a, float2 b)
{
    return make_float2(fmaf(a.x, b.x, -a.y * b.y), fmaf(a.x, b.y, a.y * b.x));
}

__device__ float2* fft2048_shared(float2* bufA, float2* bufB, const float2* tw, int tid)
{
    float2* x = bufA;
    float2* y = bufB;
#pragma unroll
    for (int ls = 0; ls < 11; ls++) {
        int half  = 1024 >> ls;
        int smask = (1 << ls) - 1;
        __syncthreads();
#pragma unroll
        for (int r = 0; r < 4; r++) {
            int i  = tid + (r << 8);
            int qq = i & smask;
            int p  = i >> ls;
            float2 a  = x[IDX(qq + (p << ls))];
            float2 bb = x[IDX(qq + ((p + half) << ls))];
            float2 w  = tw[IDX(p << ls)];
            float2 su = make_float2(a.x + bb.x, a.y + bb.y);
            float2 di = make_float2(a.x - bb.x, a.y - bb.y);
            y[IDX(qq + ((2 * p) << ls))]     = su;
            y[IDX(qq + ((2 * p + 1) << ls))] = cmulf(di, w);
        }
        float2* t = x; x = y; y = t;
    }
    __syncthreads();
    return x;
}

__global__ __launch_bounds__(256)
void autocorr_fft_kernel(const float* __restrict__ qT, const float* __restrict__ kT,
                         float2* __restrict__ Spart)
{
    __shared__ float2 bufA[2176];
    __shared__ float2 bufB[2176];
    __shared__ float2 tw[1088];
    int tid = threadIdx.x;
    int b = blockIdx.x / NGRP;
    int g = blockIdx.x % NGRP;

    for (int p = tid; p < 1024; p += 256) {
        float s, c;
        sincospif(-2.0f * (float)p / 2048.0f, &s, &c);
        tw[IDX(p)] = make_float2(c, s);
    }

    float2 acc[8];
#pragma unroll
    for (int r = 0; r < 8; r++) acc[r] = make_float2(0.0f, 0.0f);

    for (int dd = 0; dd < DG; dd++) {
        int d = g * DG + dd;
        const float* qrow = qT + ((size_t)b * Dc + d) * (size_t)Lc;
        const float* krow = kT + ((size_t)b * Dc + d) * (size_t)Lc;
        for (int t = tid; t < NFFT; t += 256)
            bufA[IDX(t)] = make_float2(qrow[t], krow[t]);

        float2* Z = fft2048_shared(bufA, bufB, tw, tid);

#pragma unroll
        for (int r = 0; r < 8; r++) {
            int f = tid + (r << 8);
            float2 zf = Z[IDX(f)];
            float2 zr = Z[IDX((NFFT - f) & (NFFT - 1))];
            float qx = 0.5f * (zf.x + zr.x), qy = 0.5f * (zf.y - zr.y);
            float dx = zf.x - zr.x,          dy = zf.y + zr.y;
            float kx = 0.5f * dy,            ky = -0.5f * dx;
            acc[r].x += qx * kx + qy * ky;
            acc[r].y += qy * kx - qx * ky;
        }
    }

    float2* outp = Spart + ((size_t)b * NGRP + g) * NFFT;
#pragma unroll
    for (int r = 0; r < 8; r++) outp[tid + (r << 8)] = acc[r];
}

__global__ __launch_bounds__(256)
void ifft_mean_kernel(const float2* __restrict__ Spart, float* __restrict__ meanv)
{
    __shared__ float2 bufA[2176];
    __shared__ float2 bufB[2176];
    __shared__ float2 tw[1088];
    int tid = threadIdx.x;
    int b = blockIdx.x;

    for (int p = tid; p < 1024; p += 256) {
        float s, c;
        sincospif(2.0f * (float)p / 2048.0f, &s, &c);
        tw[IDX(p)] = make_float2(c, s);
    }
    for (int t = tid; t < NFFT; t += 256) {
        float2 s = make_float2(0.0f, 0.0f);
        const float2* base = Spart + (size_t)b * NGRP * NFFT + t;
        for (int g2 = 0; g2 < NGRP; g2++) {
            float2 vv = base[(size_t)g2 * NFFT];
            s.x += vv.x; s.y += vv.y;
        }
        bufA[IDX(t)] = s;
    }

    float2* Z = fft2048_shared(bufA, bufB, tw, tid);

    const float scale = 1.0f / (2048.0f * 1024.0f);
    for (int t = tid; t < NFFT; t += 256)
        meanv[b * NFFT + t] = Z[IDX(t)].x * scale;
}

// ================= top-7 + softmax =================
__global__ __launch_bounds__(256)
void topk_kernel(const float* __restrict__ meanv, float* __restrict__ topW, int* __restrict__ topI)
{
    __shared__ float vals[NFFT];
    __shared__ float rv[256];
    __shared__ int   ri[256];
    __shared__ float sv[TOPK];
    __shared__ int   si[TOPK];
    int b = blockIdx.x, tid = threadIdx.x;

    for (int t = tid; t < NFFT; t += 256) vals[t] = meanv[b * NFFT + t];
    __syncthreads();

    for (int it = 0; it < TOPK; it++) {
        float best = -3.4e38f; int bi = 1 << 30;
        for (int t = tid; t < NFFT; t += 256) {
            float vv = vals[t];
            if (vv > best) { best = vv; bi = t; }
        }
        rv[tid] = best; ri[tid] = bi;
        __syncthreads();
        for (int off = 128; off > 0; off >>= 1) {
            if (tid < off) {
                float v2 = rv[tid + off]; int i2 = ri[tid + off];
                if (v2 > rv[tid] || (v2 == rv[tid] && i2 < ri[tid])) { rv[tid] = v2; ri[tid] = i2; }
            }
            __syncthreads();
        }
        if (tid == 0) { sv[it] = rv[0]; si[it] = ri[0]; vals[ri[0]] = -3.4e38f; }
        __syncthreads();
    }

    if (tid == 0) {
        float mx = sv[0], ssum = 0.0f, e[TOPK];
        for (int i = 0; i < TOPK; i++) { e[i] = expf(sv[i] - mx); ssum += e[i]; }
        for (int i = 0; i < TOPK; i++) {
            topW[b * TOPK + i] = e[i] / ssum;
            topI[b * TOPK + i] = si[i];
        }
    }
}

// ================= weighted roll-aggregate -> bf16 hi/lo =================
__global__ __launch_bounds__(256)
void agg_roll_kernel(const float* __restrict__ v, const float* __restrict__ topW,
                     const int* __restrict__ topI,
                     __nv_bfloat16* __restrict__ outH, __nv_bfloat16* __restrict__ outL)
{
    __shared__ float w[8];
    __shared__ int   dl[8];
    int row = blockIdx.x;
    int b = row >> 11;
    int l = row & (Lc - 1);
    int tid = threadIdx.x;
    if (tid < TOPK) { w[tid] = topW[b * TOPK + tid]; dl[tid] = topI[tid]; }
    __syncthreads();

    float4 acc = make_float4(0.f, 0.f, 0.f, 0.f);
#pragma unroll
    for (int i = 0; i < TOPK; i++) {
        int src = l + dl[i];
        if (src >= Lc) src -= Lc;
        float4 t = *(const float4*)(v + ((size_t)b * Lc + src) * Dc + tid * 4);
        float wi = w[i];
        acc.x = fmaf(wi, t.x, acc.x);
        acc.y = fmaf(wi, t.y, acc.y);
        acc.z = fmaf(wi, t.z, acc.z);
        acc.w = fmaf(wi, t.w, acc.w);
    }
    __nv_bfloat16 h0, h1, h2, h3, l0, l1, l2, l3;
    split1(acc.x, h0, l0); split1(acc.y, h1, l1); split1(acc.z, h2, l2); split1(acc.w, h3, l3);
    size_t i2 = (size_t)row * (Dc / 2) + tid * 2;
    ((__nv_bfloat162*)outH)[i2]     = __halves2bfloat162(h0, h1);
    ((__nv_bfloat162*)outH)[i2 + 1] = __halves2bfloat162(h2, h3);
    ((__nv_bfloat162*)outL)[i2]     = __halves2bfloat162(l0, l1);
    ((__nv_bfloat162*)outL)[i2 + 1] = __halves2bfloat162(l2, l3);
}

// ================= residual add + LayerNorm (+optional bf16 split out) =================
__global__ __launch_bounds__(256)
void add_ln_kernel(const float* __restrict__ A, const float* __restrict__ Rv,
                   const float* __restrict__ gam, const float* __restrict__ bet,
                   float* __restrict__ out,
                   __nv_bfloat16* __restrict__ outH, __nv_bfloat16* __restrict__ outL,
                   int doSplit)
{
    __shared__ float red1[8];
    __shared__ float red2[8];
    int row = blockIdx.x, tid = threadIdx.x;
    const float4* a4 = (const float4*)(A + (size_t)row * Dc);
    const float4* r4 = (const float4*)(Rv + (size_t)row * Dc);
    float4 va = a4[tid], vr = r4[tid];
    float4 s = make_float4(va.x + vr.x, va.y + vr.y, va.z + vr.z, va.w + vr.w);

    float part = s.x + s.y + s.z + s.w;
#pragma unroll
    for (int o = 16; o; o >>= 1) part += __shfl_xor_sync(0xffffffffu, part, o);
    if ((tid & 31) == 0) red1[tid >> 5] = part;
    __syncthreads();
    float tot = red1[0] + red1[1] + red1[2] + red1[3] + red1[4] + red1[5] + red1[6] + red1[7];
    float mean = tot * (1.0f / (float)Dc);

    float d0 = s.x - mean, d1 = s.y - mean, d2 = s.z - mean, d3 = s.w - mean;
    float p2 = d0 * d0 + d1 * d1 + d2 * d2 + d3 * d3;
#pragma unroll
    for (int o = 16; o; o >>= 1) p2 += __shfl_xor_sync(0xffffffffu, p2, o);
    if ((tid & 31) == 0) red2[tid >> 5] = p2;
    __syncthreads();
    float tot2 = red2[0] + red2[1] + red2[2] + red2[3] + red2[4] + red2[5] + red2[6] + red2[7];
    float var = tot2 * (1.0f / (float)Dc);
    float inv = rsqrtf(var + 1e-6f);

    float4 gg = ((const float4*)gam)[tid];
    float4 bb = ((const float4*)bet)[tid];
    float4 o4 = make_float4(d0 * inv * gg.x + bb.x,
                            d1 * inv * gg.y + bb.y,
                            d2 * inv * gg.z + bb.z,
                            d3 * inv * gg.w + bb.w);
    ((float4*)(out + (size_t)row * Dc))[tid] = o4;

    if (doSplit) {
        __nv_bfloat16 h0, h1, h2, h3, l0, l1, l2, l3;
        split1(o4.x, h0, l0); split1(o4.y, h1, l1); split1(o4.z, h2, l2); split1(o4.w, h3, l3);
        size_t i2 = (size_t)row * (Dc / 2) + tid * 2;
        ((__nv_bfloat162*)outH)[i2]     = __halves2bfloat162(h0, h1);
        ((__nv_bfloat162*)outH)[i2 + 1] = __halves2bfloat162(h2, h3);
        ((__nv_bfloat162*)outL)[i2]     = __halves2bfloat162(l0, l1);
        ((__nv_bfloat162*)outL)[i2 + 1] = __halves2bfloat162(l2, l3);
    }
}

// ================= launch =================
extern "C" void kernel_launch(void* const* d_in, const int* in_sizes, int n_in,
                              void* d_out, int out_size)
{
    const float* x    = (const float*)d_in[0];
    const float* Wq   = (const float*)d_in[1];
    const float* bq   = (const float*)d_in[2];
    const float* Wk   = (const float*)d_in[3];
    const float* bk   = (const float*)d_in[4];
    const float* Wv   = (const float*)d_in[5];
    const float* bv   = (const float*)d_in[6];
    const float* Wo   = (const float*)d_in[7];
    const float* bo   = (const float*)d_in[8];
    const float* ln1g = (const float*)d_in[9];
    const float* ln1b = (const float*)d_in[10];
    const float* c1w  = (const float*)d_in[11];
    const float* c1b  = (const float*)d_in[12];
    const float* c2w  = (const float*)d_in[13];
    const float* c2b  = (const float*)d_in[14];
    const float* ln2g = (const float*)d_in[15];
    const float* ln2b = (const float*)d_in[16];
    float* out = (float*)d_out;

    float *q, *k, *v, *qT, *kT, *meanv, *topW, *attn, *x1, *ffn2;
    float2* Spart; int* topI;
    __nv_bfloat16 *xh, *xl, *aggh, *aggl, *x1h, *x1l, *f1h, *f1l;
    __nv_bfloat16 *wqh, *wql, *wkh, *wkl, *wvh, *wvl, *woh, *wol, *c1h, *c1l, *c2h, *c2l;

    cudaGetSymbolAddress((void**)&q,     g_q);
    cudaGetSymbolAddress((void**)&k,     g_k);
    cudaGetSymbolAddress((void**)&v,     g_v);
    cudaGetSymbolAddress((void**)&qT,    g_qT);
    cudaGetSymbolAddress((void**)&kT,    g_kT);
    cudaGetSymbolAddress((void**)&Spart, g_Spart);
    cudaGetSymbolAddress((void**)&meanv, g_mean);
    cudaGetSymbolAddress((void**)&topW,  g_topW);
    cudaGetSymbolAddress((void**)&topI,  g_topI);
    cudaGetSymbolAddress((void**)&attn,  g_attn);
    cudaGetSymbolAddress((void**)&x1,    g_x1);
    cudaGetSymbolAddress((void**)&ffn2,  g_ffn2);
    cudaGetSymbolAddress((void**)&xh,    g_xh);
    cudaGetSymbolAddress((void**)&xl,    g_xl);
    cudaGetSymbolAddress((void**)&aggh,  g_aggh);
    cudaGetSymbolAddress((void**)&aggl,  g_aggl);
    cudaGetSymbolAddress((void**)&x1h,   g_x1h);
    cudaGetSymbolAddress((void**)&x1l,   g_x1l);
    cudaGetSymbolAddress((void**)&f1h,   g_f1h);
    cudaGetSymbolAddress((void**)&f1l,   g_f1l);
    cudaGetSymbolAddress((void**)&wqh,   g_wqh);
    cudaGetSymbolAddress((void**)&wql,   g_wql);
    cudaGetSymbolAddress((void**)&wkh,   g_wkh);
    cudaGetSymbolAddress((void**)&wkl,   g_wkl);
    cudaGetSymbolAddress((void**)&wvh,   g_wvh);
    cudaGetSymbolAddress((void**)&wvl,   g_wvl);
    cudaGetSymbolAddress((void**)&woh,   g_woh);
    cudaGetSymbolAddress((void**)&wol,   g_wol);
    cudaGetSymbolAddress((void**)&c1h,   g_c1h);
    cudaGetSymbolAddress((void**)&c1l,   g_c1l);
    cudaGetSymbolAddress((void**)&c2h,   g_c2h);
    cudaGetSymbolAddress((void**)&c2l,   g_c2l);

    cudaFuncSetAttribute(gemm_hmma3, cudaFuncAttributeMaxDynamicSharedMemorySize, GM_SMEM_TOTAL);

    dim3 bT32(32, 8);

    // prep: split x; transpose+split weights
    split_kernel<<<(Mc * Dc / 4 + 255) / 256, 256>>>(x, xh, xl, Mc * Dc / 4);
    wtrans_split_kernel<<<dim3(Dc / 32, Dc / 32), bT32>>>(Wq,  wqh, wql, Dc, Dc);
    wtrans_split_kernel<<<dim3(Dc / 32, Dc / 32), bT32>>>(Wk,  wkh, wkl, Dc, Dc);
    wtrans_split_kernel<<<dim3(Dc / 32, Dc / 32), bT32>>>(Wv,  wvh, wvl, Dc, Dc);
    wtrans_split_kernel<<<dim3(Dc / 32, Dc / 32), bT32>>>(Wo,  woh, wol, Dc, Dc);
    wtrans_split_kernel<<<dim3(Fc / 32, Dc / 32), bT32>>>(c1w, c1h, c1l, Dc, Fc);
    wtrans_split_kernel<<<dim3(Dc / 32, Fc / 32), bT32>>>(c2w, c2h, c2l, Fc, Dc);

    const int MB = Mc / 128;          // 128
    const int NB_D = Dc / 128;        // 8
    const int NB_F = Fc / 128;        // 32
    int gridD = MB * NB_D;            // 1024
    int gridF = MB * NB_F;            // 4096

    gemm_hmma3<<<gridD, 256, GM_SMEM_TOTAL>>>(xh, xl, wqh, wql, bq, q, nullptr, nullptr, Mc, Dc, Dc, 0, NB_D);
    gemm_hmma3<<<gridD, 256, GM_SMEM_TOTAL>>>(xh, xl, wkh, wkl, bk, k, nullptr, nullptr, Mc, Dc, Dc, 0, NB_D);
    gemm_hmma3<<<gridD, 256, GM_SMEM_TOTAL>>>(xh, xl, wvh, wvl, bv, v, nullptr, nullptr, Mc, Dc, Dc, 0, NB_D);

    dim3 gT(Lc / 32, Dc / 32, Bc);
    transpose_kernel<<<gT, bT32>>>(q, qT);
    transpose_kernel<<<gT, bT32>>>(k, kT);

    autocorr_fft_kernel<<<Bc * NGRP, 256>>>(qT, kT, Spart);
    ifft_mean_kernel<<<Bc, 256>>>(Spart, meanv);
    topk_kernel<<<Bc, 256>>>(meanv, topW, topI);
    agg_roll_kernel<<<Mc, 256>>>(v, topW, topI, aggh, aggl);

    gemm_hmma3<<<gridD, 256, GM_SMEM_TOTAL>>>(aggh, aggl, woh, wol, bo, attn, nullptr, nullptr, Mc, Dc, Dc, 0, NB_D);
    add_ln_kernel<<<Mc, 256>>>(x, attn, ln1g, ln1b, x1, x1h, x1l, 1);

    gemm_hmma3<<<gridF, 256, GM_SMEM_TOTAL>>>(x1h, x1l, c1h, c1l, c1b, nullptr, f1h, f1l, Mc, Fc, Dc, 1, NB_F);
    gemm_hmma3<<<gridD, 256, GM_SMEM_TOTAL>>>(f1h, f1l, c2h, c2l, c2b, ffn2, nullptr, nullptr, Mc, Dc, Fc, 0, NB_D);
    add_ln_kernel<<<Mc, 256>>>(x1, ffn2, ln2g, ln2b, out, nullptr, nullptr, 0);
}

// round 14
// speedup vs baseline: 3.0115x; 1.2576x over previous
#include <cuda_runtime.h>
#include <cuda_bf16.h>
#include <cuda_fp16.h>
#include <cstdint>

#define Bc 8
#define Lc 2048
#define Dc 1024
#define Fc 4096
#define Mc (Bc*Lc)          // 16384 rows
#define TOPK 7
#define NFFT 2048
#define DG 16               // d-channels per FFT block
#define NGRP (Dc/DG)        // 64 groups

// ================= scratch (device globals) =================
__device__ float  g_v[Mc*Dc];
__device__ float  g_qT[Mc*Dc];
__device__ float  g_kT[Mc*Dc];
__device__ float2 g_Spart[Bc*NGRP*NFFT];
__device__ float  g_mean[Bc*NFFT];
__device__ float  g_topW[Bc*TOPK];
__device__ int    g_topI[Bc*TOPK];
__device__ float  g_attn[Mc*Dc];
__device__ float  g_x1[Mc*Dc];
__device__ float  g_ffn2[Mc*Dc];

// bf16 splits (QKV path)
__device__ __nv_bfloat16 g_xh[Mc*Dc],  g_xl[Mc*Dc];
__device__ __nv_bfloat16 g_wqh[Dc*Dc], g_wql[Dc*Dc];
__device__ __nv_bfloat16 g_wkh[Dc*Dc], g_wkl[Dc*Dc];
__device__ __nv_bfloat16 g_wvh[Dc*Dc], g_wvl[Dc*Dc];
// fp16 (O / FFN path, 2-term)
__device__ __half g_aggh[Mc*Dc], g_aggl[Mc*Dc];
__device__ __half g_x1h[Mc*Dc],  g_x1l[Mc*Dc];
__device__ __half g_f1h[Mc*Fc],  g_f1l[Mc*Fc];
__device__ __half g_woh[Dc*Dc];
__device__ __half g_c1h[Fc*Dc];
__device__ __half g_c2h[Dc*Fc];

// ================= split helpers =================
__device__ __forceinline__ void split1(float v, __nv_bfloat16& h, __nv_bfloat16& l) {
    h = __float2bfloat16(v);
    l = __float2bfloat16(v - __bfloat162float(h));
}
__device__ __forceinline__ void split1h(float v, __half& h, __half& l) {
    h = __float2half_rn(v);
    l = __float2half_rn(v - __half2float(h));
}

__global__ __launch_bounds__(256)
void split_kernel(const float* __restrict__ in, __nv_bfloat16* __restrict__ hi,
                  __nv_bfloat16* __restrict__ lo, int n4)
{
    int i = blockIdx.x * 256 + threadIdx.x;
    if (i >= n4) return;
    float4 v = ((const float4*)in)[i];
    __nv_bfloat16 h0, h1, h2, h3, l0, l1, l2, l3;
    split1(v.x, h0, l0); split1(v.y, h1, l1); split1(v.z, h2, l2); split1(v.w, h3, l3);
    __nv_bfloat162* hp = (__nv_bfloat162*)hi;
    __nv_bfloat162* lp = (__nv_bfloat162*)lo;
    hp[2*i]   = __halves2bfloat162(h0, h1);
    hp[2*i+1] = __halves2bfloat162(h2, h3);
    lp[2*i]   = __halves2bfloat162(l0, l1);
    lp[2*i+1] = __halves2bfloat162(l2, l3);
}

// W[K,N] fp32 -> T[N,K] bf16 hi/lo
__global__ void wtrans_split_kernel(const float* __restrict__ W, __nv_bfloat16* __restrict__ Th,
                                    __nv_bfloat16* __restrict__ Tl, int K, int N)
{
    __shared__ float tile[32][33];
    int k0 = blockIdx.y << 5, n0 = blockIdx.x << 5;
    int tx = threadIdx.x, ty = threadIdx.y;
#pragma unroll
    for (int i = ty; i < 32; i += 8)
        tile[i][tx] = W[(size_t)(k0 + i) * N + n0 + tx];
    __syncthreads();
#pragma unroll
    for (int i = ty; i < 32; i += 8) {
        float v = tile[tx][i];
        __nv_bfloat16 h, l; split1(v, h, l);
        size_t o = (size_t)(n0 + i) * K + k0 + tx;
        Th[o] = h; Tl[o] = l;
    }
}

// W[K,N] fp32 -> T[N,K] fp16 (single)
__global__ void wtrans_f16_kernel(const float* __restrict__ W, __half* __restrict__ Th,
                                  int K, int N)
{
    __shared__ float tile[32][33];
    int k0 = blockIdx.y << 5, n0 = blockIdx.x << 5;
    int tx = threadIdx.x, ty = threadIdx.y;
#pragma unroll
    for (int i = ty; i < 32; i += 8)
        tile[i][tx] = W[(size_t)(k0 + i) * N + n0 + tx];
    __syncthreads();
#pragma unroll
    for (int i = ty; i < 32; i += 8)
        Th[(size_t)(n0 + i) * K + k0 + tx] = __float2half_rn(tile[tx][i]);
}

// ================= HMMA GEMM (mma.sync) =================
// TERMS==3 (bf16): D = Ah*Bh + Ah*Bl + Al*Bh
// TERMS==2 (fp16): D = Ah*Bh + Al*Bh   (B single fp16)
// A[M,K] row-major; B[N,K] row-major (pre-transposed weights). M tile 128, N tile 128, BK 32.
// mode 0: C fp32 = D + bias
// mode 1: relu(D+bias) split -> Chi/Clo fp16
// mode 2: fp32 transposed out: C[(b*Dc + n)*Lc + l] (N must be Dc)

#define GM_PADB 80                       // bytes per smem row (64B data + 16 pad)
#define MAT_BYTES (128*GM_PADB)          // 10240

__device__ __forceinline__ uint32_t smem_u32(const void* p) {
    uint32_t a;
    asm("{ .reg .u64 t; cvta.to.shared.u64 t, %1; cvt.u32.u64 %0, t; }" : "=r"(a) : "l"(p));
    return a;
}
__device__ __forceinline__ void cp16(uint32_t s, const void* g) {
    asm volatile("cp.async.cg.shared.global [%0], [%1], 16;" :: "r"(s), "l"(g) : "memory");
}
__device__ __forceinline__ void ldsm4(uint32_t* r, uint32_t a) {
    asm volatile("ldmatrix.sync.aligned.m8n8.x4.shared.b16 {%0,%1,%2,%3}, [%4];"
                 : "=r"(r[0]), "=r"(r[1]), "=r"(r[2]), "=r"(r[3]) : "r"(a));
}
__device__ __forceinline__ void mma_bf16(float* d, const uint32_t* a, uint32_t b0, uint32_t b1) {
    asm volatile("mma.sync.aligned.m16n8k16.row.col.f32.bf16.bf16.f32 "
                 "{%0,%1,%2,%3}, {%4,%5,%6,%7}, {%8,%9}, {%0,%1,%2,%3};"
                 : "+f"(d[0]), "+f"(d[1]), "+f"(d[2]), "+f"(d[3])
                 : "r"(a[0]), "r"(a[1]), "r"(a[2]), "r"(a[3]), "r"(b0), "r"(b1));
}
__device__ __forceinline__ void mma_f16(float* d, const uint32_t* a, uint32_t b0, uint32_t b1) {
    asm volatile("mma.sync.aligned.m16n8k16.row.col.f32.f16.f16.f32 "
                 "{%0,%1,%2,%3}, {%4,%5,%6,%7}, {%8,%9}, {%0,%1,%2,%3};"
                 : "+f"(d[0]), "+f"(d[1]), "+f"(d[2]), "+f"(d[3])
                 : "r"(a[0]), "r"(a[1]), "r"(a[2]), "r"(a[3]), "r"(b0), "r"(b1));
}

template<int NMAT>
__device__ __forceinline__ void load_chunk(uint32_t sbase,
    const uint16_t* pAh, const uint16_t* pAl,
    const uint16_t* pBh, const uint16_t* pBl,
    int K, int ko, int tid)
{
    const uint16_t* srcs[4];
    srcs[0] = pAh + ko; srcs[1] = pAl + ko; srcs[2] = pBh + ko;
    srcs[3] = (NMAT == 4) ? (pBl + ko) : (pAh + ko);
#pragma unroll
    for (int m = 0; m < NMAT; m++) {
        const uint16_t* src = srcs[m];
        uint32_t mb = sbase + m * MAT_BYTES;
#pragma unroll
        for (int t = 0; t < 2; t++) {
            int idx = tid + t * 256;
            int r = idx >> 2, cs = idx & 3;
            cp16(mb + r * GM_PADB + cs * 16, src + (size_t)r * K + cs * 8);
        }
    }
}

template<int TERMS, bool ISBF16>
__global__ __launch_bounds__(256)
void gemm_hmma(const uint16_t* __restrict__ Ahi, const uint16_t* __restrict__ Alo,
               const uint16_t* __restrict__ Bhi, const uint16_t* __restrict__ Blo,
               const float* __restrict__ bias,
               float* __restrict__ C, __half* __restrict__ Chi, __half* __restrict__ Clo,
               int N, int K, int mode, int NB)
{
    constexpr int NMAT = (TERMS == 2) ? 3 : 4;
    constexpr uint32_t SBYTES = NMAT * MAT_BYTES;
    extern __shared__ char smem[];
    uint32_t sb = smem_u32(smem);
    int tid = threadIdx.x, lane = tid & 31, warp = tid >> 5;

    // CTA swizzle: panels of 8 along M for L2 reuse
    int bid = blockIdx.x;
    int panel  = bid / (8 * NB);
    int within = bid - panel * (8 * NB);
    int bm = panel * 8 + (within & 7);
    int bn = within >> 3;
    size_t row0 = (size_t)bm * 128, col0 = (size_t)bn * 128;

    const uint16_t* pAh = Ahi + row0 * (size_t)K;
    const uint16_t* pAl = Alo + row0 * (size_t)K;
    const uint16_t* pBh = Bhi + col0 * (size_t)K;
    const uint16_t* pBl = (TERMS == 3) ? (Blo + col0 * (size_t)K) : pBh;

    load_chunk<NMAT>(sb, pAh, pAl, pBh, pBl, K, 0, tid);
    asm volatile("cp.async.commit_group;" ::: "memory");

    int g = lane >> 3, rl = lane & 7;
    int wm = warp >> 1, wn = warp & 1;
    uint32_t aoff[2][2], boff[4][2];
#pragma unroll
    for (int i = 0; i < 2; i++)
#pragma unroll
        for (int ks = 0; ks < 2; ks++) {
            int row = wm * 32 + i * 16 + (g & 1) * 8 + rl;
            int col = ks * 16 + (g >> 1) * 8;
            aoff[i][ks] = row * GM_PADB + col * 2;
        }
#pragma unroll
    for (int j = 0; j < 4; j++)
#pragma unroll
        for (int ks = 0; ks < 2; ks++) {
            int row = wn * 64 + j * 16 + ((g >> 1) & 1) * 8 + rl;
            int col = ks * 16 + (g & 1) * 8;
            boff[j][ks] = 2 * MAT_BYTES + row * GM_PADB + col * 2;
        }

    float acc[2][8][4];
#pragma unroll
    for (int i = 0; i < 2; i++)
#pragma unroll
        for (int j = 0; j < 8; j++)
#pragma unroll
            for (int r = 0; r < 4; r++) acc[i][j][r] = 0.0f;

    int NC = K >> 5;
    for (int c = 0; c < NC; c++) {
        uint32_t sstage = sb + (uint32_t)(c & 1) * SBYTES;
        if (c + 1 < NC) {
            load_chunk<NMAT>(sb + (uint32_t)((c + 1) & 1) * SBYTES,
                             pAh, pAl, pBh, pBl, K, (c + 1) << 5, tid);
            asm volatile("cp.async.commit_group;" ::: "memory");
            asm volatile("cp.async.wait_group 1;" ::: "memory");
        } else {
            asm volatile("cp.async.wait_group 0;" ::: "memory");
        }
        __syncthreads();

#pragma unroll
        for (int ks = 0; ks < 2; ks++) {
            uint32_t ah[2][4], al[2][4];
            ldsm4(ah[0], sstage + aoff[0][ks]);
            ldsm4(ah[1], sstage + aoff[1][ks]);
            ldsm4(al[0], sstage + MAT_BYTES + aoff[0][ks]);
            ldsm4(al[1], sstage + MAT_BYTES + aoff[1][ks]);
#pragma unroll
            for (int j = 0; j < 4; j++) {
                uint32_t bh[4], bl[4];
                ldsm4(bh, sstage + boff[j][ks]);
                if (TERMS == 3) ldsm4(bl, sstage + MAT_BYTES + boff[j][ks]);
#pragma unroll
                for (int i = 0; i < 2; i++) {
                    if (ISBF16) {
                        mma_bf16(acc[i][2*j],   ah[i], bh[0], bh[1]);
                        if (TERMS == 3) mma_bf16(acc[i][2*j], ah[i], bl[0], bl[1]);
                        mma_bf16(acc[i][2*j],   al[i], bh[0], bh[1]);
                        mma_bf16(acc[i][2*j+1], ah[i], bh[2], bh[3]);
                        if (TERMS == 3) mma_bf16(acc[i][2*j+1], ah[i], bl[2], bl[3]);
                        mma_bf16(acc[i][2*j+1], al[i], bh[2], bh[3]);
                    } else {
                        mma_f16(acc[i][2*j],   ah[i], bh[0], bh[1]);
                        if (TERMS == 3) mma_f16(acc[i][2*j], ah[i], bl[0], bl[1]);
                        mma_f16(acc[i][2*j],   al[i], bh[0], bh[1]);
                        mma_f16(acc[i][2*j+1], ah[i], bh[2], bh[3]);
                        if (TERMS == 3) mma_f16(acc[i][2*j+1], ah[i], bl[2], bl[3]);
                        mma_f16(acc[i][2*j+1], al[i], bh[2], bh[3]);
                    }
                }
            }
        }
        __syncthreads();
    }

    int tr = lane >> 2, tc = (lane & 3) * 2;

    if (mode == 2) {
        // stage fp32 tile in smem, write transposed [b, d, l]
        float* tp = (float*)smem;
        const int PAD = 133;
#pragma unroll
        for (int i = 0; i < 2; i++)
#pragma unroll
            for (int j = 0; j < 8; j++) {
                int r = wm * 32 + i * 16 + tr;
                int cl = wn * 64 + j * 8 + tc;
                tp[r * PAD + cl]           = acc[i][j][0];
                tp[r * PAD + cl + 1]       = acc[i][j][1];
                tp[(r + 8) * PAD + cl]     = acc[i][j][2];
                tp[(r + 8) * PAD + cl + 1] = acc[i][j][3];
            }
        __syncthreads();
        int b = (int)(row0 >> 11);
        int l0 = (int)(row0 & 2047);
#pragma unroll 1
        for (int it = 0; it < 16; it++) {
            int idx = tid + it * 256;        // 0..4095
            int d = idx >> 5;                // 0..127
            int r4 = (idx & 31) * 4;         // 0..124
            float bv = __ldg(bias + col0 + d);
            float4 o;
            o.x = tp[(r4 + 0) * PAD + d] + bv;
            o.y = tp[(r4 + 1) * PAD + d] + bv;
            o.z = tp[(r4 + 2) * PAD + d] + bv;
            o.w = tp[(r4 + 3) * PAD + d] + bv;
            *(float4*)(C + ((size_t)b * Dc + col0 + d) * (size_t)Lc + l0 + r4) = o;
        }
        return;
    }

#pragma unroll
    for (int i = 0; i < 2; i++) {
#pragma unroll
        for (int j = 0; j < 8; j++) {
            size_t r0 = row0 + wm * 32 + i * 16 + tr;
            size_t cl = col0 + wn * 64 + j * 8 + tc;
            float b0 = __ldg(bias + cl), b1 = __ldg(bias + cl + 1);
            float v00 = acc[i][j][0] + b0, v01 = acc[i][j][1] + b1;
            float v10 = acc[i][j][2] + b0, v11 = acc[i][j][3] + b1;
            if (mode == 0) {
                *(float2*)(C + r0 * (size_t)N + cl)       = make_float2(v00, v01);
                *(float2*)(C + (r0 + 8) * (size_t)N + cl) = make_float2(v10, v11);
            } else {
                v00 = fmaxf(v00, 0.f); v01 = fmaxf(v01, 0.f);
                v10 = fmaxf(v10, 0.f); v11 = fmaxf(v11, 0.f);
                __half h0,h1,h2,h3, l0,l1,l2,l3;
                split1h(v00,h0,l0); split1h(v01,h1,l1); split1h(v10,h2,l2); split1h(v11,h3,l3);
                *(__half2*)(Chi + r0 * (size_t)N + cl)       = __halves2half2(h0, h1);
                *(__half2*)(Chi + (r0 + 8) * (size_t)N + cl) = __halves2half2(h2, h3);
                *(__half2*)(Clo + r0 * (size_t)N + cl)       = __halves2half2(l0, l1);
                *(__half2*)(Clo + (r0 + 8) * (size_t)N + cl) = __halves2half2(l2, l3);
            }
        }
    }
}

// ================= shared-memory 2048-point Stockham FFT =================
#define IDX(i) ((i) + ((i) >> 4))

__device__ __forceinline__ float2 cmulf(float2 a, float2 b)
{
    return make_float2(fmaf(a.x, b.x, -a.y * b.y), fmaf(a.x, b.y, a.y * b.x));
}

__device__ float2* fft2048_shared(float2* bufA, float2* bufB, const float2* tw, int tid)
{
    float2* x = bufA;
    float2* y = bufB;
#pragma unroll
    for (int ls = 0; ls < 11; ls++) {
        int half  = 1024 >> ls;
        int smask = (1 << ls) - 1;
        __syncthreads();
#pragma unroll
        for (int r = 0; r < 4; r++) {
            int i  = tid + (r << 8);
            int qq = i & smask;
            int p  = i >> ls;
            float2 a  = x[IDX(qq + (p << ls))];
            float2 bb = x[IDX(qq + ((p + half) << ls))];
            float2 w  = tw[IDX(p << ls)];
            float2 su = make_float2(a.x + bb.x, a.y + bb.y);
            float2 di = make_float2(a.x - bb.x, a.y - bb.y);
            y[IDX(qq + ((2 * p) << ls))]     = su;
            y[IDX(qq + ((2 * p + 1) << ls))] = cmulf(di, w);
        }
        float2* t = x; x = y; y = t;
    }
    __syncthreads();
    return x;
}

__global__ __launch_bounds__(256)
void autocorr_fft_kernel(const float* __restrict__ qT, const float* __restrict__ kT,
                         float2* __restrict__ Spart)
{
    __shared__ float2 bufA[2176];
    __shared__ float2 bufB[2176];
    __shared__ float2 tw[1088];
    int tid = threadIdx.x;
    int b = blockIdx.x / NGRP;
    int g = blockIdx.x % NGRP;

    for (int p = tid; p < 1024; p += 256) {
        float s, c;
        sincospif(-2.0f * (float)p / 2048.0f, &s, &c);
        tw[IDX(p)] = make_float2(c, s);
    }

    float2 acc[8];
#pragma unroll
    for (int r = 0; r < 8; r++) acc[r] = make_float2(0.0f, 0.0f);

    for (int dd = 0; dd < DG; dd++) {
        int d = g * DG + dd;
        const float* qrow = qT + ((size_t)b * Dc + d) * (size_t)Lc;
        const float* krow = kT + ((size_t)b * Dc + d) * (size_t)Lc;
        for (int t = tid; t < NFFT; t += 256)
            bufA[IDX(t)] = make_float2(qrow[t], krow[t]);

        float2* Z = fft2048_shared(bufA, bufB, tw, tid);

#pragma unroll
        for (int r = 0; r < 8; r++) {
            int f = tid + (r << 8);
            float2 zf = Z[IDX(f)];
            float2 zr = Z[IDX((NFFT - f) & (NFFT - 1))];
            float qx = 0.5f * (zf.x + zr.x), qy = 0.5f * (zf.y - zr.y);
            float dx = zf.x - zr.x,          dy = zf.y + zr.y;
            float kx = 0.5f * dy,            ky = -0.5f * dx;
            acc[r].x += qx * kx + qy * ky;
            acc[r].y += qy * kx - qx * ky;
        }
    }

    float2* outp = Spart + ((size_t)b * NGRP + g) * NFFT;
#pragma unroll
    for (int r = 0; r < 8; r++) outp[tid + (r << 8)] = acc[r];
}

__global__ __launch_bounds__(256)
void ifft_mean_kernel(const float2* __restrict__ Spart, float* __restrict__ meanv)
{
    __shared__ float2 bufA[2176];
    __shared__ float2 bufB[2176];
    __shared__ float2 tw[1088];
    int tid = threadIdx.x;
    int b = blockIdx.x;

    for (int p = tid; p < 1024; p += 256) {
        float s, c;
        sincospif(2.0f * (float)p / 2048.0f, &s, &c);
        tw[IDX(p)] = make_float2(c, s);
    }
    for (int t = tid; t < NFFT; t += 256) {
        float2 s = make_float2(0.0f, 0.0f);
        const float2* base = Spart + (size_t)b * NGRP * NFFT + t;
        for (int g2 = 0; g2 < NGRP; g2++) {
            float2 vv = base[(size_t)g2 * NFFT];
            s.x += vv.x; s.y += vv.y;
        }
        bufA[IDX(t)] = s;
    }

    float2* Z = fft2048_shared(bufA, bufB, tw, tid);

    const float scale = 1.0f / (2048.0f * 1024.0f);
    for (int t = tid; t < NFFT; t += 256)
        meanv[b * NFFT + t] = Z[IDX(t)].x * scale;
}

// ================= top-7 + softmax =================
__global__ __launch_bounds__(256)
void topk_kernel(const float* __restrict__ meanv, float* __restrict__ topW, int* __restrict__ topI)
{
    __shared__ float vals[NFFT];
    __shared__ float rv[256];
    __shared__ int   ri[256];
    __shared__ float sv[TOPK];
    __shared__ int   si[TOPK];
    int b = blockIdx.x, tid = threadIdx.x;

    for (int t = tid; t < NFFT; t += 256) vals[t] = meanv[b * NFFT + t];
    __syncthreads();

    for (int it = 0; it < TOPK; it++) {
        float best = -3.4e38f; int bi = 1 << 30;
        for (int t = tid; t < NFFT; t += 256) {
            float vv = vals[t];
            if (vv > best) { best = vv; bi = t; }
        }
        rv[tid] = best; ri[tid] = bi;
        __syncthreads();
        for (int off = 128; off > 0; off >>= 1) {
            if (tid < off) {
                float v2 = rv[tid + off]; int i2 = ri[tid + off];
                if (v2 > rv[tid] || (v2 == rv[tid] && i2 < ri[tid])) { rv[tid] = v2; ri[tid] = i2; }
            }
            __syncthreads();
        }
        if (tid == 0) { sv[it] = rv[0]; si[it] = ri[0]; vals[ri[0]] = -3.4e38f; }
        __syncthreads();
    }

    if (tid == 0) {
        float mx = sv[0], ssum = 0.0f, e[TOPK];
        for (int i = 0; i < TOPK; i++) { e[i] = expf(sv[i] - mx); ssum += e[i]; }
        for (int i = 0; i < TOPK; i++) {
            topW[b * TOPK + i] = e[i] / ssum;
            topI[b * TOPK + i] = si[i];
        }
    }
}

// ================= weighted roll-aggregate -> fp16 hi/lo =================
__global__ __launch_bounds__(256)
void agg_roll_kernel(const float* __restrict__ v, const float* __restrict__ topW,
                     const int* __restrict__ topI,
                     __half* __restrict__ outH, __half* __restrict__ outL)
{
    __shared__ float w[8];
    __shared__ int   dl[8];
    int row = blockIdx.x;
    int b = row >> 11;
    int l = row & (Lc - 1);
    int tid = threadIdx.x;
    if (tid < TOPK) { w[tid] = topW[b * TOPK + tid]; dl[tid] = topI[tid]; }
    __syncthreads();

    float4 acc = make_float4(0.f, 0.f, 0.f, 0.f);
#pragma unroll
    for (int i = 0; i < TOPK; i++) {
        int src = l + dl[i];
        if (src >= Lc) src -= Lc;
        float4 t = *(const float4*)(v + ((size_t)b * Lc + src) * Dc + tid * 4);
        float wi = w[i];
        acc.x = fmaf(wi, t.x, acc.x);
        acc.y = fmaf(wi, t.y, acc.y);
        acc.z = fmaf(wi, t.z, acc.z);
        acc.w = fmaf(wi, t.w, acc.w);
    }
    __half h0, h1, h2, h3, l0, l1, l2, l3;
    split1h(acc.x, h0, l0); split1h(acc.y, h1, l1); split1h(acc.z, h2, l2); split1h(acc.w, h3, l3);
    size_t i2 = (size_t)row * (Dc / 2) + tid * 2;
    ((__half2*)outH)[i2]     = __halves2half2(h0, h1);
    ((__half2*)outH)[i2 + 1] = __halves2half2(h2, h3);
    ((__half2*)outL)[i2]     = __halves2half2(l0, l1);
    ((__half2*)outL)[i2 + 1] = __halves2half2(l2, l3);
}

// ================= residual add + LayerNorm (+optional fp16 split out) =================
__global__ __launch_bounds__(256)
void add_ln_kernel(const float* __restrict__ A, const float* __restrict__ Rv,
                   const float* __restrict__ gam, const float* __restrict__ bet,
                   float* __restrict__ out,
                   __half* __restrict__ outH, __half* __restrict__ outL,
                   int doSplit)
{
    __shared__ float red1[8];
    __shared__ float red2[8];
    int row = blockIdx.x, tid = threadIdx.x;
    const float4* a4 = (const float4*)(A + (size_t)row * Dc);
    const float4* r4 = (const float4*)(Rv + (size_t)row * Dc);
    float4 va = a4[tid], vr = r4[tid];
    float4 s = make_float4(va.x + vr.x, va.y + vr.y, va.z + vr.z, va.w + vr.w);

    float part = s.x + s.y + s.z + s.w;
#pragma unroll
    for (int o = 16; o; o >>= 1) part += __shfl_xor_sync(0xffffffffu, part, o);
    if ((tid & 31) == 0) red1[tid >> 5] = part;
    __syncthreads();
    float tot = red1[0] + red1[1] + red1[2] + red1[3] + red1[4] + red1[5] + red1[6] + red1[7];
    float mean = tot * (1.0f / (float)Dc);

    float d0 = s.x - mean, d1 = s.y - mean, d2 = s.z - mean, d3 = s.w - mean;
    float p2 = d0 * d0 + d1 * d1 + d2 * d2 + d3 * d3;
#pragma unroll
    for (int o = 16; o; o >>= 1) p2 += __shfl_xor_sync(0xffffffffu, p2, o);
    if ((tid & 31) == 0) red2[tid >> 5] = p2;
    __syncthreads();
    float tot2 = red2[0] + red2[1] + red2[2] + red2[3] + red2[4] + red2[5] + red2[6] + red2[7];
    float var = tot2 * (1.0f / (float)Dc);
    float inv = rsqrtf(var + 1e-6f);

    float4 gg = ((const float4*)gam)[tid];
    float4 bb = ((const float4*)bet)[tid];
    float4 o4 = make_float4(d0 * inv * gg.x + bb.x,
                            d1 * inv * gg.y + bb.y,
                            d2 * inv * gg.z + bb.z,
                            d3 * inv * gg.w + bb.w);
    ((float4*)(out + (size_t)row * Dc))[tid] = o4;

    if (doSplit) {
        __half h0, h1, h2, h3, l0, l1, l2, l3;
        split1h(o4.x, h0, l0); split1h(o4.y, h1, l1); split1h(o4.z, h2, l2); split1h(o4.w, h3, l3);
        size_t i2 = (size_t)row * (Dc / 2) + tid * 2;
        ((__half2*)outH)[i2]     = __halves2half2(h0, h1);
        ((__half2*)outH)[i2 + 1] = __halves2half2(h2, h3);
        ((__half2*)outL)[i2]     = __halves2half2(l0, l1);
        ((__half2*)outL)[i2 + 1] = __halves2half2(l2, l3);
    }
}

// ================= launch =================
extern "C" void kernel_launch(void* const* d_in, const int* in_sizes, int n_in,
                              void* d_out, int out_size)
{
    const float* x    = (const float*)d_in[0];
    const float* Wq   = (const float*)d_in[1];
    const float* bq   = (const float*)d_in[2];
    const float* Wk   = (const float*)d_in[3];
    const float* bk   = (const float*)d_in[4];
    const float* Wv   = (const float*)d_in[5];
    const float* bv   = (const float*)d_in[6];
    const float* Wo   = (const float*)d_in[7];
    const float* bo   = (const float*)d_in[8];
    const float* ln1g = (const float*)d_in[9];
    const float* ln1b = (const float*)d_in[10];
    const float* c1w  = (const float*)d_in[11];
    const float* c1b  = (const float*)d_in[12];
    const float* c2w  = (const float*)d_in[13];
    const float* c2b  = (const float*)d_in[14];
    const float* ln2g = (const float*)d_in[15];
    const float* ln2b = (const float*)d_in[16];
    float* out = (float*)d_out;

    float *v, *qT, *kT, *meanv, *topW, *attn, *x1, *ffn2;
    float2* Spart; int* topI;
    __nv_bfloat16 *xh, *xl, *wqh, *wql, *wkh, *wkl, *wvh, *wvl;
    __half *aggh, *aggl, *x1h, *x1l, *f1h, *f1l, *woh, *c1h, *c2h;

    cudaGetSymbolAddress((void**)&v,     g_v);
    cudaGetSymbolAddress((void**)&qT,    g_qT);
    cudaGetSymbolAddress((void**)&kT,    g_kT);
    cudaGetSymbolAddress((void**)&Spart, g_Spart);
    cudaGetSymbolAddress((void**)&meanv, g_mean);
    cudaGetSymbolAddress((void**)&topW,  g_topW);
    cudaGetSymbolAddress((void**)&topI,  g_topI);
    cudaGetSymbolAddress((void**)&attn,  g_attn);
    cudaGetSymbolAddress((void**)&x1,    g_x1);
    cudaGetSymbolAddress((void**)&ffn2,  g_ffn2);
    cudaGetSymbolAddress((void**)&xh,    g_xh);
    cudaGetSymbolAddress((void**)&xl,    g_xl);
    cudaGetSymbolAddress((void**)&wqh,   g_wqh);
    cudaGetSymbolAddress((void**)&wql,   g_wql);
    cudaGetSymbolAddress((void**)&wkh,   g_wkh);
    cudaGetSymbolAddress((void**)&wkl,   g_wkl);
    cudaGetSymbolAddress((void**)&wvh,   g_wvh);
    cudaGetSymbolAddress((void**)&wvl,   g_wvl);
    cudaGetSymbolAddress((void**)&aggh,  g_aggh);
    cudaGetSymbolAddress((void**)&aggl,  g_aggl);
    cudaGetSymbolAddress((void**)&x1h,   g_x1h);
    cudaGetSymbolAddress((void**)&x1l,   g_x1l);
    cudaGetSymbolAddress((void**)&f1h,   g_f1h);
    cudaGetSymbolAddress((void**)&f1l,   g_f1l);
    cudaGetSymbolAddress((void**)&woh,   g_woh);
    cudaGetSymbolAddress((void**)&c1h,   g_c1h);
    cudaGetSymbolAddress((void**)&c2h,   g_c2h);

    const int SMEM3 = 2 * 4 * MAT_BYTES;   // 81920 (also covers mode2 staging 68KB)
    const int SMEM2 = 2 * 3 * MAT_BYTES;   // 61440
    cudaFuncSetAttribute(gemm_hmma<3, true>,  cudaFuncAttributeMaxDynamicSharedMemorySize, SMEM3);
    cudaFuncSetAttribute(gemm_hmma<2, false>, cudaFuncAttributeMaxDynamicSharedMemorySize, SMEM2);

    dim3 bT32(32, 8);

    // prep
    split_kernel<<<(Mc * Dc / 4 + 255) / 256, 256>>>(x, xh, xl, Mc * Dc / 4);
    wtrans_split_kernel<<<dim3(Dc / 32, Dc / 32), bT32>>>(Wq,  wqh, wql, Dc, Dc);
    wtrans_split_kernel<<<dim3(Dc / 32, Dc / 32), bT32>>>(Wk,  wkh, wkl, Dc, Dc);
    wtrans_split_kernel<<<dim3(Dc / 32, Dc / 32), bT32>>>(Wv,  wvh, wvl, Dc, Dc);
    wtrans_f16_kernel<<<dim3(Dc / 32, Dc / 32), bT32>>>(Wo,  woh, Dc, Dc);
    wtrans_f16_kernel<<<dim3(Fc / 32, Dc / 32), bT32>>>(c1w, c1h, Dc, Fc);
    wtrans_f16_kernel<<<dim3(Dc / 32, Fc / 32), bT32>>>(c2w, c2h, Fc, Dc);

    const int MB = Mc / 128;          // 128
    const int NB_D = Dc / 128;        // 8
    const int NB_F = Fc / 128;        // 32
    int gridD = MB * NB_D;            // 1024
    int gridF = MB * NB_F;            // 4096

    // QKV: bf16 3-term; Q,K with fused transposed epilogue
    gemm_hmma<3, true><<<gridD, 256, SMEM3>>>((const uint16_t*)xh, (const uint16_t*)xl,
        (const uint16_t*)wqh, (const uint16_t*)wql, bq, qT, nullptr, nullptr, Dc, Dc, 2, NB_D);
    gemm_hmma<3, true><<<gridD, 256, SMEM3>>>((const uint16_t*)xh, (const uint16_t*)xl,
        (const uint16_t*)wkh, (const uint16_t*)wkl, bk, kT, nullptr, nullptr, Dc, Dc, 2, NB_D);
    gemm_hmma<3, true><<<gridD, 256, SMEM3>>>((const uint16_t*)xh, (const uint16_t*)xl,
        (const uint16_t*)wvh, (const uint16_t*)wvl, bv, v, nullptr, nullptr, Dc, Dc, 0, NB_D);

    autocorr_fft_kernel<<<Bc * NGRP, 256>>>(qT, kT, Spart);
    ifft_mean_kernel<<<Bc, 256>>>(Spart, meanv);
    topk_kernel<<<Bc, 256>>>(meanv, topW, topI);
    agg_roll_kernel<<<Mc, 256>>>(v, topW, topI, aggh, aggl);

    // O / FFN: fp16 2-term
    gemm_hmma<2, false><<<gridD, 256, SMEM2>>>((const uint16_t*)aggh, (const uint16_t*)aggl,
        (const uint16_t*)woh, nullptr, bo, attn, nullptr, nullptr, Dc, Dc, 0, NB_D);
    add_ln_kernel<<<Mc, 256>>>(x, attn, ln1g, ln1b, x1, x1h, x1l, 1);

    gemm_hmma<2, false><<<gridF, 256, SMEM2>>>((const uint16_t*)x1h, (const uint16_t*)x1l,
        (const uint16_t*)c1h, nullptr, c1b, nullptr, f1h, f1l, Fc, Dc, 1, NB_F);
    gemm_hmma<2, false><<<gridD, 256, SMEM2>>>((const uint16_t*)f1h, (const uint16_t*)f1l,
        (const uint16_t*)c2h, nullptr, c2b, ffn2, nullptr, nullptr, Dc, Fc, 0, NB_D);
    add_ln_kernel<<<Mc, 256>>>(x1, ffn2, ln2g, ln2b, out, nullptr, nullptr, 0);
}

// round 17
// speedup vs baseline: 4.2103x; 1.3981x over previous
#include <cuda_runtime.h>
#include <cuda_bf16.h>
#include <cuda_fp16.h>
#include <cstdint>

#define Bc 8
#define Lc 2048
#define Dc 1024
#define Fc 4096
#define Mc (Bc*Lc)          // 16384 rows
#define TOPK 7
#define NFFT 2048
#define DG 16               // d-channels per FFT block
#define NGRP (Dc/DG)        // 64 groups

// ================= scratch (device globals) =================
__device__ float  g_v[Mc*Dc];
__device__ float  g_qT[Mc*Dc];
__device__ float  g_kT[Mc*Dc];
__device__ float2 g_Spart[Bc*NGRP*NFFT];
__device__ float  g_mean[Bc*NFFT];
__device__ float  g_topW[Bc*TOPK];
__device__ int    g_topI[Bc*TOPK];
__device__ float  g_attn[Mc*Dc];
__device__ float  g_x1[Mc*Dc];
__device__ float  g_ffn2[Mc*Dc];

// bf16 splits (QKV path, 3-term)
__device__ __nv_bfloat16 g_xh[Mc*Dc],  g_xl[Mc*Dc];
__device__ __nv_bfloat16 g_wqh[Dc*Dc], g_wql[Dc*Dc];
__device__ __nv_bfloat16 g_wkh[Dc*Dc], g_wkl[Dc*Dc];
__device__ __nv_bfloat16 g_wvh[Dc*Dc], g_wvl[Dc*Dc];
// fp16 (O / FFN path, 1-term)
__device__ __half g_aggh[Mc*Dc];
__device__ __half g_x1h[Mc*Dc];
__device__ __half g_f1h[Mc*Fc];
__device__ __half g_woh[Dc*Dc];
__device__ __half g_c1h[Fc*Dc];
__device__ __half g_c2h[Dc*Fc];

// ================= split helpers =================
__device__ __forceinline__ void split1(float v, __nv_bfloat16& h, __nv_bfloat16& l) {
    h = __float2bfloat16(v);
    l = __float2bfloat16(v - __bfloat162float(h));
}

__global__ __launch_bounds__(256)
void split_kernel(const float* __restrict__ in, __nv_bfloat16* __restrict__ hi,
                  __nv_bfloat16* __restrict__ lo, int n4)
{
    int i = blockIdx.x * 256 + threadIdx.x;
    if (i >= n4) return;
    float4 v = ((const float4*)in)[i];
    __nv_bfloat16 h0, h1, h2, h3, l0, l1, l2, l3;
    split1(v.x, h0, l0); split1(v.y, h1, l1); split1(v.z, h2, l2); split1(v.w, h3, l3);
    __nv_bfloat162* hp = (__nv_bfloat162*)hi;
    __nv_bfloat162* lp = (__nv_bfloat162*)lo;
    hp[2*i]   = __halves2bfloat162(h0, h1);
    hp[2*i+1] = __halves2bfloat162(h2, h3);
    lp[2*i]   = __halves2bfloat162(l0, l1);
    lp[2*i+1] = __halves2bfloat162(l2, l3);
}

// W[K,N] fp32 -> T[N,K] bf16 hi/lo
__global__ void wtrans_split_kernel(const float* __restrict__ W, __nv_bfloat16* __restrict__ Th,
                                    __nv_bfloat16* __restrict__ Tl, int K, int N)
{
    __shared__ float tile[32][33];
    int k0 = blockIdx.y << 5, n0 = blockIdx.x << 5;
    int tx = threadIdx.x, ty = threadIdx.y;
#pragma unroll
    for (int i = ty; i < 32; i += 8)
        tile[i][tx] = W[(size_t)(k0 + i) * N + n0 + tx];
    __syncthreads();
#pragma unroll
    for (int i = ty; i < 32; i += 8) {
        float v = tile[tx][i];
        __nv_bfloat16 h, l; split1(v, h, l);
        size_t o = (size_t)(n0 + i) * K + k0 + tx;
        Th[o] = h; Tl[o] = l;
    }
}

// W[K,N] fp32 -> T[N,K] fp16 (single)
__global__ void wtrans_f16_kernel(const float* __restrict__ W, __half* __restrict__ Th,
                                  int K, int N)
{
    __shared__ float tile[32][33];
    int k0 = blockIdx.y << 5, n0 = blockIdx.x << 5;
    int tx = threadIdx.x, ty = threadIdx.y;
#pragma unroll
    for (int i = ty; i < 32; i += 8)
        tile[i][tx] = W[(size_t)(k0 + i) * N + n0 + tx];
    __syncthreads();
#pragma unroll
    for (int i = ty; i < 32; i += 8)
        Th[(size_t)(n0 + i) * K + k0 + tx] = __float2half_rn(tile[tx][i]);
}

// ================= HMMA GEMM (mma.sync) =================
// TERMS==3 (bf16): D = Ah*Bh + Ah*Bl + Al*Bh
// TERMS==1 (fp16): D = Ah*Bh
// A[M,K] row-major; B[N,K] row-major (pre-transposed weights). Tile 128x128, BK 32.
// mode 0: C fp32 = D + bias
// mode 1: relu(D+bias) -> Chi fp16 (single)
// mode 2: fp32 transposed out: C[(b*Dc + n)*Lc + l] (N must be Dc)

#define GM_PADB 80                       // bytes per smem row (64B data + 16 pad)
#define MAT_BYTES (128*GM_PADB)          // 10240

__device__ __forceinline__ uint32_t smem_u32(const void* p) {
    uint32_t a;
    asm("{ .reg .u64 t; cvta.to.shared.u64 t, %1; cvt.u32.u64 %0, t; }" : "=r"(a) : "l"(p));
    return a;
}
__device__ __forceinline__ void cp16(uint32_t s, const void* g) {
    asm volatile("cp.async.cg.shared.global [%0], [%1], 16;" :: "r"(s), "l"(g) : "memory");
}
__device__ __forceinline__ void ldsm4(uint32_t* r, uint32_t a) {
    asm volatile("ldmatrix.sync.aligned.m8n8.x4.shared.b16 {%0,%1,%2,%3}, [%4];"
                 : "=r"(r[0]), "=r"(r[1]), "=r"(r[2]), "=r"(r[3]) : "r"(a));
}
__device__ __forceinline__ void mma_bf16(float* d, const uint32_t* a, uint32_t b0, uint32_t b1) {
    asm volatile("mma.sync.aligned.m16n8k16.row.col.f32.bf16.bf16.f32 "
                 "{%0,%1,%2,%3}, {%4,%5,%6,%7}, {%8,%9}, {%0,%1,%2,%3};"
                 : "+f"(d[0]), "+f"(d[1]), "+f"(d[2]), "+f"(d[3])
                 : "r"(a[0]), "r"(a[1]), "r"(a[2]), "r"(a[3]), "r"(b0), "r"(b1));
}
__device__ __forceinline__ void mma_f16(float* d, const uint32_t* a, uint32_t b0, uint32_t b1) {
    asm volatile("mma.sync.aligned.m16n8k16.row.col.f32.f16.f16.f32 "
                 "{%0,%1,%2,%3}, {%4,%5,%6,%7}, {%8,%9}, {%0,%1,%2,%3};"
                 : "+f"(d[0]), "+f"(d[1]), "+f"(d[2]), "+f"(d[3])
                 : "r"(a[0]), "r"(a[1]), "r"(a[2]), "r"(a[3]), "r"(b0), "r"(b1));
}

// slot layout: [Ah][Al (TERMS>=2)][Bh][Bl (TERMS==3)]
template<int TERMS>
struct GemmCfg {
    static constexpr int NMAT  = (TERMS == 3) ? 4 : (TERMS == 2) ? 3 : 2;
    static constexpr int BSLOT = (TERMS == 1) ? 1 : 2;
};

template<int TERMS>
__device__ __forceinline__ void load_chunk(uint32_t sbase,
    const uint16_t* pAh, const uint16_t* pAl,
    const uint16_t* pBh, const uint16_t* pBl,
    int K, int ko, int tid)
{
    constexpr int NMAT  = GemmCfg<TERMS>::NMAT;
    constexpr int BSLOT = GemmCfg<TERMS>::BSLOT;
    const uint16_t* srcs[4];
    int n = 0;
    srcs[n++] = pAh + ko;
    if (TERMS >= 2) srcs[n++] = pAl + ko;
    srcs[n++] = pBh + ko;
    if (TERMS == 3) srcs[n++] = pBl + ko;
    (void)BSLOT;
#pragma unroll
    for (int m = 0; m < NMAT; m++) {
        const uint16_t* src = srcs[m];
        uint32_t mb = sbase + m * MAT_BYTES;
#pragma unroll
        for (int t = 0; t < 2; t++) {
            int idx = tid + t * 256;
            int r = idx >> 2, cs = idx & 3;
            cp16(mb + r * GM_PADB + cs * 16, src + (size_t)r * K + cs * 8);
        }
    }
}

template<int TERMS, bool ISBF16>
__global__ __launch_bounds__(256)
void gemm_hmma(const uint16_t* __restrict__ Ahi, const uint16_t* __restrict__ Alo,
               const uint16_t* __restrict__ Bhi, const uint16_t* __restrict__ Blo,
               const float* __restrict__ bias,
               float* __restrict__ C, __half* __restrict__ Chi,
               int N, int K, int mode, int NB)
{
    constexpr int NMAT  = GemmCfg<TERMS>::NMAT;
    constexpr int BSLOT = GemmCfg<TERMS>::BSLOT;
    constexpr uint32_t SBYTES = NMAT * MAT_BYTES;
    extern __shared__ char smem[];
    uint32_t sb = smem_u32(smem);
    int tid = threadIdx.x, lane = tid & 31, warp = tid >> 5;

    // CTA swizzle: panels of 8 along M for L2 reuse
    int bid = blockIdx.x;
    int panel  = bid / (8 * NB);
    int within = bid - panel * (8 * NB);
    int bm = panel * 8 + (within & 7);
    int bn = within >> 3;
    size_t row0 = (size_t)bm * 128, col0 = (size_t)bn * 128;

    const uint16_t* pAh = Ahi + row0 * (size_t)K;
    const uint16_t* pAl = (TERMS >= 2) ? (Alo + row0 * (size_t)K) : pAh;
    const uint16_t* pBh = Bhi + col0 * (size_t)K;
    const uint16_t* pBl = (TERMS == 3) ? (Blo + col0 * (size_t)K) : pBh;

    load_chunk<TERMS>(sb, pAh, pAl, pBh, pBl, K, 0, tid);
    asm volatile("cp.async.commit_group;" ::: "memory");

    int g = lane >> 3, rl = lane & 7;
    int wm = warp >> 1, wn = warp & 1;
    uint32_t aoff[2][2], boff[4][2];
#pragma unroll
    for (int i = 0; i < 2; i++)
#pragma unroll
        for (int ks = 0; ks < 2; ks++) {
            int row = wm * 32 + i * 16 + (g & 1) * 8 + rl;
            int col = ks * 16 + (g >> 1) * 8;
            aoff[i][ks] = row * GM_PADB + col * 2;
        }
#pragma unroll
    for (int j = 0; j < 4; j++)
#pragma unroll
        for (int ks = 0; ks < 2; ks++) {
            int row = wn * 64 + j * 16 + ((g >> 1) & 1) * 8 + rl;
            int col = ks * 16 + (g & 1) * 8;
            boff[j][ks] = BSLOT * MAT_BYTES + row * GM_PADB + col * 2;
        }

    float acc[2][8][4];
#pragma unroll
    for (int i = 0; i < 2; i++)
#pragma unroll
        for (int j = 0; j < 8; j++)
#pragma unroll
            for (int r = 0; r < 4; r++) acc[i][j][r] = 0.0f;

    int NC = K >> 5;
    for (int c = 0; c < NC; c++) {
        uint32_t sstage = sb + (uint32_t)(c & 1) * SBYTES;
        if (c + 1 < NC) {
            load_chunk<TERMS>(sb + (uint32_t)((c + 1) & 1) * SBYTES,
                              pAh, pAl, pBh, pBl, K, (c + 1) << 5, tid);
            asm volatile("cp.async.commit_group;" ::: "memory");
            asm volatile("cp.async.wait_group 1;" ::: "memory");
        } else {
            asm volatile("cp.async.wait_group 0;" ::: "memory");
        }
        __syncthreads();

#pragma unroll
        for (int ks = 0; ks < 2; ks++) {
            uint32_t ah[2][4], al[2][4];
            ldsm4(ah[0], sstage + aoff[0][ks]);
            ldsm4(ah[1], sstage + aoff[1][ks]);
            if (TERMS >= 2) {
                ldsm4(al[0], sstage + MAT_BYTES + aoff[0][ks]);
                ldsm4(al[1], sstage + MAT_BYTES + aoff[1][ks]);
            }
#pragma unroll
            for (int j = 0; j < 4; j++) {
                uint32_t bh[4], bl[4];
                ldsm4(bh, sstage + boff[j][ks]);
                if (TERMS == 3) ldsm4(bl, sstage + MAT_BYTES + boff[j][ks]);
#pragma unroll
                for (int i = 0; i < 2; i++) {
                    if (ISBF16) {
                        mma_bf16(acc[i][2*j],   ah[i], bh[0], bh[1]);
                        if (TERMS == 3) mma_bf16(acc[i][2*j], ah[i], bl[0], bl[1]);
                        if (TERMS >= 2) mma_bf16(acc[i][2*j], al[i], bh[0], bh[1]);
                        mma_bf16(acc[i][2*j+1], ah[i], bh[2], bh[3]);
                        if (TERMS == 3) mma_bf16(acc[i][2*j+1], ah[i], bl[2], bl[3]);
                        if (TERMS >= 2) mma_bf16(acc[i][2*j+1], al[i], bh[2], bh[3]);
                    } else {
                        mma_f16(acc[i][2*j],   ah[i], bh[0], bh[1]);
                        if (TERMS == 3) mma_f16(acc[i][2*j], ah[i], bl[0], bl[1]);
                        if (TERMS >= 2) mma_f16(acc[i][2*j], al[i], bh[0], bh[1]);
                        mma_f16(acc[i][2*j+1], ah[i], bh[2], bh[3]);
                        if (TERMS == 3) mma_f16(acc[i][2*j+1], ah[i], bl[2], bl[3]);
                        if (TERMS >= 2) mma_f16(acc[i][2*j+1], al[i], bh[2], bh[3]);
                    }
                }
            }
        }
        __syncthreads();
    }

    int tr = lane >> 2, tc = (lane & 3) * 2;

    if (mode == 2) {
        // stage fp32 tile in smem, write transposed [b, d, l]
        float* tp = (float*)smem;
        const int PAD = 133;
#pragma unroll
        for (int i = 0; i < 2; i++)
#pragma unroll
            for (int j = 0; j < 8; j++) {
                int r = wm * 32 + i * 16 + tr;
                int cl = wn * 64 + j * 8 + tc;
                tp[r * PAD + cl]           = acc[i][j][0];
                tp[r * PAD + cl + 1]       = acc[i][j][1];
                tp[(r + 8) * PAD + cl]     = acc[i][j][2];
                tp[(r + 8) * PAD + cl + 1] = acc[i][j][3];
            }
        __syncthreads();
        int b = (int)(row0 >> 11);
        int l0 = (int)(row0 & 2047);
#pragma unroll 1
        for (int it = 0; it < 16; it++) {
            int idx = tid + it * 256;        // 0..4095
            int d = idx >> 5;                // 0..127
            int r4 = (idx & 31) * 4;         // 0..124
            float bv = __ldg(bias + col0 + d);
            float4 o;
            o.x = tp[(r4 + 0) * PAD + d] + bv;
            o.y = tp[(r4 + 1) * PAD + d] + bv;
            o.z = tp[(r4 + 2) * PAD + d] + bv;
            o.w = tp[(r4 + 3) * PAD + d] + bv;
            *(float4*)(C + ((size_t)b * Dc + col0 + d) * (size_t)Lc + l0 + r4) = o;
        }
        return;
    }

#pragma unroll
    for (int i = 0; i < 2; i++) {
#pragma unroll
        for (int j = 0; j < 8; j++) {
            size_t r0 = row0 + wm * 32 + i * 16 + tr;
            size_t cl = col0 + wn * 64 + j * 8 + tc;
            float b0 = __ldg(bias + cl), b1 = __ldg(bias + cl + 1);
            float v00 = acc[i][j][0] + b0, v01 = acc[i][j][1] + b1;
            float v10 = acc[i][j][2] + b0, v11 = acc[i][j][3] + b1;
            if (mode == 0) {
                *(float2*)(C + r0 * (size_t)N + cl)       = make_float2(v00, v01);
                *(float2*)(C + (r0 + 8) * (size_t)N + cl) = make_float2(v10, v11);
            } else {
                v00 = fmaxf(v00, 0.f); v01 = fmaxf(v01, 0.f);
                v10 = fmaxf(v10, 0.f); v11 = fmaxf(v11, 0.f);
                *(__half2*)(Chi + r0 * (size_t)N + cl) =
                    __halves2half2(__float2half_rn(v00), __float2half_rn(v01));
                *(__half2*)(Chi + (r0 + 8) * (size_t)N + cl) =
                    __halves2half2(__float2half_rn(v10), __float2half_rn(v11));
            }
        }
    }
}

// ================= shared-memory 2048-point Stockham FFT =================
#define IDX(i) ((i) + ((i) >> 4))

__device__ __forceinline__ float2 cmulf(float2 a, float2 b)
{
    return make_float2(fmaf(a.x, b.x, -a.y * b.y), fmaf(a.x, b.y, a.y * b.x));
}

__device__ float2* fft2048_shared(float2* bufA, float2* bufB, const float2* tw, int tid)
{
    float2* x = bufA;
    float2* y = bufB;
#pragma unroll
    for (int ls = 0; ls < 11; ls++) {
        int half  = 1024 >> ls;
        int smask = (1 << ls) - 1;
        __syncthreads();
#pragma unroll
        for (int r = 0; r < 4; r++) {
            int i  = tid + (r << 8);
            int qq = i & smask;
            int p  = i >> ls;
            float2 a  = x[IDX(qq + (p << ls))];
            float2 bb = x[IDX(qq + ((p + half) << ls))];
            float2 w  = tw[IDX(p << ls)];
            float2 su = make_float2(a.x + bb.x, a.y + bb.y);
            float2 di = make_float2(a.x - bb.x, a.y - bb.y);
            y[IDX(qq + ((2 * p) << ls))]     = su;
            y[IDX(qq + ((2 * p + 1) << ls))] = cmulf(di, w);
        }
        float2* t = x; x = y; y = t;
    }
    __syncthreads();
    return x;
}

__global__ __launch_bounds__(256)
void autocorr_fft_kernel(const float* __restrict__ qT, const float* __restrict__ kT,
                         float2* __restrict__ Spart)
{
    __shared__ float2 bufA[2176];
    __shared__ float2 bufB[2176];
    __shared__ float2 tw[1088];
    int tid = threadIdx.x;
    int b = blockIdx.x / NGRP;
    int g = blockIdx.x % NGRP;

    for (int p = tid; p < 1024; p += 256) {
        float s, c;
        sincospif(-2.0f * (float)p / 2048.0f, &s, &c);
        tw[IDX(p)] = make_float2(c, s);
    }

    float2 acc[8];
#pragma unroll
    for (int r = 0; r < 8; r++) acc[r] = make_float2(0.0f, 0.0f);

    for (int dd = 0; dd < DG; dd++) {
        int d = g * DG + dd;
        const float* qrow = qT + ((size_t)b * Dc + d) * (size_t)Lc;
        const float* krow = kT + ((size_t)b * Dc + d) * (size_t)Lc;
        for (int t = tid; t < NFFT; t += 256)
            bufA[IDX(t)] = make_float2(qrow[t], krow[t]);

        float2* Z = fft2048_shared(bufA, bufB, tw, tid);

#pragma unroll
        for (int r = 0; r < 8; r++) {
            int f = tid + (r << 8);
            float2 zf = Z[IDX(f)];
            float2 zr = Z[IDX((NFFT - f) & (NFFT - 1))];
            float qx = 0.5f * (zf.x + zr.x), qy = 0.5f * (zf.y - zr.y);
            float dx = zf.x - zr.x,          dy = zf.y + zr.y;
            float kx = 0.5f * dy,            ky = -0.5f * dx;
            acc[r].x += qx * kx + qy * ky;
            acc[r].y += qy * kx - qx * ky;
        }
    }

    float2* outp = Spart + ((size_t)b * NGRP + g) * NFFT;
#pragma unroll
    for (int r = 0; r < 8; r++) outp[tid + (r << 8)] = acc[r];
}

__global__ __launch_bounds__(256)
void ifft_mean_kernel(const float2* __restrict__ Spart, float* __restrict__ meanv)
{
    __shared__ float2 bufA[2176];
    __shared__ float2 bufB[2176];
    __shared__ float2 tw[1088];
    int tid = threadIdx.x;
    int b = blockIdx.x;

    for (int p = tid; p < 1024; p += 256) {
        float s, c;
        sincospif(2.0f * (float)p / 2048.0f, &s, &c);
        tw[IDX(p)] = make_float2(c, s);
    }
    for (int t = tid; t < NFFT; t += 256) {
        float2 s = make_float2(0.0f, 0.0f);
        const float2* base = Spart + (size_t)b * NGRP * NFFT + t;
        for (int g2 = 0; g2 < NGRP; g2++) {
            float2 vv = base[(size_t)g2 * NFFT];
            s.x += vv.x; s.y += vv.y;
        }
        bufA[IDX(t)] = s;
    }

    float2* Z = fft2048_shared(bufA, bufB, tw, tid);

    const float scale = 1.0f / (2048.0f * 1024.0f);
    for (int t = tid; t < NFFT; t += 256)
        meanv[b * NFFT + t] = Z[IDX(t)].x * scale;
}

// ================= top-7 + softmax =================
__global__ __launch_bounds__(256)
void topk_kernel(const float* __restrict__ meanv, float* __restrict__ topW, int* __restrict__ topI)
{
    __shared__ float vals[NFFT];
    __shared__ float rv[256];
    __shared__ int   ri[256];
    __shared__ float sv[TOPK];
    __shared__ int   si[TOPK];
    int b = blockIdx.x, tid = threadIdx.x;

    for (int t = tid; t < NFFT; t += 256) vals[t] = meanv[b * NFFT + t];
    __syncthreads();

    for (int it = 0; it < TOPK; it++) {
        float best = -3.4e38f; int bi = 1 << 30;
        for (int t = tid; t < NFFT; t += 256) {
            float vv = vals[t];
            if (vv > best) { best = vv; bi = t; }
        }
        rv[tid] = best; ri[tid] = bi;
        __syncthreads();
        for (int off = 128; off > 0; off >>= 1) {
            if (tid < off) {
                float v2 = rv[tid + off]; int i2 = ri[tid + off];
                if (v2 > rv[tid] || (v2 == rv[tid] && i2 < ri[tid])) { rv[tid] = v2; ri[tid] = i2; }
            }
            __syncthreads();
        }
        if (tid == 0) { sv[it] = rv[0]; si[it] = ri[0]; vals[ri[0]] = -3.4e38f; }
        __syncthreads();
    }

    if (tid == 0) {
        float mx = sv[0], ssum = 0.0f, e[TOPK];
        for (int i = 0; i < TOPK; i++) { e[i] = expf(sv[i] - mx); ssum += e[i]; }
        for (int i = 0; i < TOPK; i++) {
            topW[b * TOPK + i] = e[i] / ssum;
            topI[b * TOPK + i] = si[i];
        }
    }
}

// ================= weighted roll-aggregate -> fp16 =================
__global__ __launch_bounds__(256)
void agg_roll_kernel(const float* __restrict__ v, const float* __restrict__ topW,
                     const int* __restrict__ topI, __half* __restrict__ outH)
{
    __shared__ float w[8];
    __shared__ int   dl[8];
    int row = blockIdx.x;
    int b = row >> 11;
    int l = row & (Lc - 1);
    int tid = threadIdx.x;
    if (tid < TOPK) { w[tid] = topW[b * TOPK + tid]; dl[tid] = topI[tid]; }
    __syncthreads();

    float4 acc = make_float4(0.f, 0.f, 0.f, 0.f);
#pragma unroll
    for (int i = 0; i < TOPK; i++) {
        int src = l + dl[i];
        if (src >= Lc) src -= Lc;
        float4 t = *(const float4*)(v + ((size_t)b * Lc + src) * Dc + tid * 4);
        float wi = w[i];
        acc.x = fmaf(wi, t.x, acc.x);
        acc.y = fmaf(wi, t.y, acc.y);
        acc.z = fmaf(wi, t.z, acc.z);
        acc.w = fmaf(wi, t.w, acc.w);
    }
    size_t i2 = (size_t)row * (Dc / 2) + tid * 2;
    ((__half2*)outH)[i2]     = __halves2half2(__float2half_rn(acc.x), __float2half_rn(acc.y));
    ((__half2*)outH)[i2 + 1] = __halves2half2(__float2half_rn(acc.z), __float2half_rn(acc.w));
}

// ================= residual add + LayerNorm (+optional fp16 out) =================
__global__ __launch_bounds__(256)
void add_ln_kernel(const float* __restrict__ A, const float* __restrict__ Rv,
                   const float* __restrict__ gam, const float* __restrict__ bet,
                   float* __restrict__ out, __half* __restrict__ outH, int doHalf)
{
    __shared__ float red1[8];
    __shared__ float red2[8];
    int row = blockIdx.x, tid = threadIdx.x;
    const float4* a4 = (const float4*)(A + (size_t)row * Dc);
    const float4* r4 = (const float4*)(Rv + (size_t)row * Dc);
    float4 va = a4[tid], vr = r4[tid];
    float4 s = make_float4(va.x + vr.x, va.y + vr.y, va.z + vr.z, va.w + vr.w);

    float part = s.x + s.y + s.z + s.w;
#pragma unroll
    for (int o = 16; o; o >>= 1) part += __shfl_xor_sync(0xffffffffu, part, o);
    if ((tid & 31) == 0) red1[tid >> 5] = part;
    __syncthreads();
    float tot = red1[0] + red1[1] + red1[2] + red1[3] + red1[4] + red1[5] + red1[6] + red1[7];
    float mean = tot * (1.0f / (float)Dc);

    float d0 = s.x - mean, d1 = s.y - mean, d2 = s.z - mean, d3 = s.w - mean;
    float p2 = d0 * d0 + d1 * d1 + d2 * d2 + d3 * d3;
#pragma unroll
    for (int o = 16; o; o >>= 1) p2 += __shfl_xor_sync(0xffffffffu, p2, o);
    if ((tid & 31) == 0) red2[tid >> 5] = p2;
    __syncthreads();
    float tot2 = red2[0] + red2[1] + red2[2] + red2[3] + red2[4] + red2[5] + red2[6] + red2[7];
    float var = tot2 * (1.0f / (float)Dc);
    float inv = rsqrtf(var + 1e-6f);

    float4 gg = ((const float4*)gam)[tid];
    float4 bb = ((const float4*)bet)[tid];
    float4 o4 = make_float4(d0 * inv * gg.x + bb.x,
                            d1 * inv * gg.y + bb.y,
                            d2 * inv * gg.z + bb.z,
                            d3 * inv * gg.w + bb.w);
    ((float4*)(out + (size_t)row * Dc))[tid] = o4;

    if (doHalf) {
        size_t i2 = (size_t)row * (Dc / 2) + tid * 2;
        ((__half2*)outH)[i2]     = __halves2half2(__float2half_rn(o4.x), __float2half_rn(o4.y));
        ((__half2*)outH)[i2 + 1] = __halves2half2(__float2half_rn(o4.z), __float2half_rn(o4.w));
    }
}

// ================= launch =================
extern "C" void kernel_launch(void* const* d_in, const int* in_sizes, int n_in,
                              void* d_out, int out_size)
{
    const float* x    = (const float*)d_in[0];
    const float* Wq   = (const float*)d_in[1];
    const float* bq   = (const float*)d_in[2];
    const float* Wk   = (const float*)d_in[3];
    const float* bk   = (const float*)d_in[4];
    const float* Wv   = (const float*)d_in[5];
    const float* bv   = (const float*)d_in[6];
    const float* Wo   = (const float*)d_in[7];
    const float* bo   = (const float*)d_in[8];
    const float* ln1g = (const float*)d_in[9];
    const float* ln1b = (const float*)d_in[10];
    const float* c1w  = (const float*)d_in[11];
    const float* c1b  = (const float*)d_in[12];
    const float* c2w  = (const float*)d_in[13];
    const float* c2b  = (const float*)d_in[14];
    const float* ln2g = (const float*)d_in[15];
    const float* ln2b = (const float*)d_in[16];
    float* out = (float*)d_out;

    float *v, *qT, *kT, *meanv, *topW, *attn, *x1, *ffn2;
    float2* Spart; int* topI;
    __nv_bfloat16 *xh, *xl, *wqh, *wql, *wkh, *wkl, *wvh, *wvl;
    __half *aggh, *x1h, *f1h, *woh, *c1h, *c2h;

    cudaGetSymbolAddress((void**)&v,     g_v);
    cudaGetSymbolAddress((void**)&qT,    g_qT);
    cudaGetSymbolAddress((void**)&kT,    g_kT);
    cudaGetSymbolAddress((void**)&Spart, g_Spart);
    cudaGetSymbolAddress((void**)&meanv, g_mean);
    cudaGetSymbolAddress((void**)&topW,  g_topW);
    cudaGetSymbolAddress((void**)&topI,  g_topI);
    cudaGetSymbolAddress((void**)&attn,  g_attn);
    cudaGetSymbolAddress((void**)&x1,    g_x1);
    cudaGetSymbolAddress((void**)&ffn2,  g_ffn2);
    cudaGetSymbolAddress((void**)&xh,    g_xh);
    cudaGetSymbolAddress((void**)&xl,    g_xl);
    cudaGetSymbolAddress((void**)&wqh,   g_wqh);
    cudaGetSymbolAddress((void**)&wql,   g_wql);
    cudaGetSymbolAddress((void**)&wkh,   g_wkh);
    cudaGetSymbolAddress((void**)&wkl,   g_wkl);
    cudaGetSymbolAddress((void**)&wvh,   g_wvh);
    cudaGetSymbolAddress((void**)&wvl,   g_wvl);
    cudaGetSymbolAddress((void**)&aggh,  g_aggh);
    cudaGetSymbolAddress((void**)&x1h,   g_x1h);
    cudaGetSymbolAddress((void**)&f1h,   g_f1h);
    cudaGetSymbolAddress((void**)&woh,   g_woh);
    cudaGetSymbolAddress((void**)&c1h,   g_c1h);
    cudaGetSymbolAddress((void**)&c2h,   g_c2h);

    const int SMEM3 = 2 * 4 * MAT_BYTES;   // 81920 (covers mode2 staging 68KB)
    const int SMEM1 = 2 * 2 * MAT_BYTES;   // 40960
    cudaFuncSetAttribute(gemm_hmma<3, true>,  cudaFuncAttributeMaxDynamicSharedMemorySize, SMEM3);
    cudaFuncSetAttribute(gemm_hmma<1, false>, cudaFuncAttributeMaxDynamicSharedMemorySize, SMEM1);

    dim3 bT32(32, 8);

    // prep
    split_kernel<<<(Mc * Dc / 4 + 255) / 256, 256>>>(x, xh, xl, Mc * Dc / 4);
    wtrans_split_kernel<<<dim3(Dc / 32, Dc / 32), bT32>>>(Wq,  wqh, wql, Dc, Dc);
    wtrans_split_kernel<<<dim3(Dc / 32, Dc / 32), bT32>>>(Wk,  wkh, wkl, Dc, Dc);
    wtrans_split_kernel<<<dim3(Dc / 32, Dc / 32), bT32>>>(Wv,  wvh, wvl, Dc, Dc);
    wtrans_f16_kernel<<<dim3(Dc / 32, Dc / 32), bT32>>>(Wo,  woh, Dc, Dc);
    wtrans_f16_kernel<<<dim3(Fc / 32, Dc / 32), bT32>>>(c1w, c1h, Dc, Fc);
    wtrans_f16_kernel<<<dim3(Dc / 32, Fc / 32), bT32>>>(c2w, c2h, Fc, Dc);

    const int MB = Mc / 128;          // 128
    const int NB_D = Dc / 128;        // 8
    const int NB_F = Fc / 128;        // 32
    int gridD = MB * NB_D;            // 1024
    int gridF = MB * NB_F;            // 4096

    // QKV: bf16 3-term; Q,K with fused transposed epilogue
    gemm_hmma<3, true><<<gridD, 256, SMEM3>>>((const uint16_t*)xh, (const uint16_t*)xl,
        (const uint16_t*)wqh, (const uint16_t*)wql, bq, qT, nullptr, Dc, Dc, 2, NB_D);
    gemm_hmma<3, true><<<gridD, 256, SMEM3>>>((const uint16_t*)xh, (const uint16_t*)xl,
        (const uint16_t*)wkh, (const uint16_t*)wkl, bk, kT, nullptr, Dc, Dc, 2, NB_D);
    gemm_hmma<3, true><<<gridD, 256, SMEM3>>>((const uint16_t*)xh, (const uint16_t*)xl,
        (const uint16_t*)wvh, (const uint16_t*)wvl, bv, v, nullptr, Dc, Dc, 0, NB_D);

    autocorr_fft_kernel<<<Bc * NGRP, 256>>>(qT, kT, Spart);
    ifft_mean_kernel<<<Bc, 256>>>(Spart, meanv);
    topk_kernel<<<Bc, 256>>>(meanv, topW, topI);
    agg_roll_kernel<<<Mc, 256>>>(v, topW, topI, aggh);

    // O / FFN: fp16 1-term
    gemm_hmma<1, false><<<gridD, 256, SMEM1>>>((const uint16_t*)aggh, nullptr,
        (const uint16_t*)woh, nullptr, bo, attn, nullptr, Dc, Dc, 0, NB_D);
    add_ln_kernel<<<Mc, 256>>>(x, attn, ln1g, ln1b, x1, x1h, 1);

    gemm_hmma<1, false><<<gridF, 256, SMEM1>>>((const uint16_t*)x1h, nullptr,
        (const uint16_t*)c1h, nullptr, c1b, nullptr, f1h, Fc, Dc, 1, NB_F);
    gemm_hmma<1, false><<<gridD, 256, SMEM1>>>((const uint16_t*)f1h, nullptr,
        (const uint16_t*)c2h, nullptr, c2b, ffn2, nullptr, Dc, Fc, 0, NB_D);
    add_ln_kernel<<<Mc, 256>>>(x1, ffn2, ln2g, ln2b, out, nullptr, 0);
}